// round 1
// baseline (speedup 1.0000x reference)
#include <cuda_runtime.h>

#define NUM_CU 100000
#define NUM_CI 50000
#define DIM 64
#define NUM_LAYERS 3
#define NUM_EDGES 1600000
#define EPS 1e-8f

// ---------------- scratch (device globals; no allocation allowed) ----------------
__device__ float g_w[NUM_EDGES];                 // softplus weights
__device__ float g_deg_u[NUM_CU];
__device__ float g_deg_i[NUM_CI];
__device__ int   g_cnt_u[NUM_CU];
__device__ int   g_cnt_i[NUM_CI];
__device__ int   g_cur_u[NUM_CU];
__device__ int   g_cur_i[NUM_CI];
__device__ int   g_off_u[NUM_CU + 1];
__device__ int   g_off_i[NUM_CI + 1];
__device__ int2  g_bu[NUM_EDGES];                // user buckets: {item_idx, norm bits}
__device__ int2  g_bi[NUM_EDGES];                // item buckets: {user_idx, norm bits}
__device__ __align__(16) float g_u[2][NUM_CU * DIM];   // ping-pong user embeddings
__device__ __align__(16) float g_it[2][NUM_CI * DIM];  // ping-pong item embeddings

// ---------------- kernels ----------------

__global__ void zero_kernel() {
    int i = blockIdx.x * blockDim.x + threadIdx.x;
    if (i < NUM_CU) { g_deg_u[i] = 0.f; g_cnt_u[i] = 0; g_cur_u[i] = 0; }
    if (i < NUM_CI) { g_deg_i[i] = 0.f; g_cnt_i[i] = 0; g_cur_i[i] = 0; }
}

__global__ void edge_w_kernel(const float* __restrict__ logit,
                              const int* __restrict__ cu,
                              const int* __restrict__ ci) {
    int e = blockIdx.x * blockDim.x + threadIdx.x;
    if (e >= NUM_EDGES) return;
    float x = logit[e];
    // softplus = logaddexp(x, 0), numerically stable
    float w = (x > 0.f ? x + log1pf(expf(-x)) : log1pf(expf(x))) + EPS;
    g_w[e] = w;
    int a = cu[e], b = ci[e];
    atomicAdd(&g_deg_u[a], w);
    atomicAdd(&g_deg_i[b], w);
    atomicAdd(&g_cnt_u[a], 1);
    atomicAdd(&g_cnt_i[b], 1);
}

// Single-block exclusive scan per array (block 0: users, block 1: items).
__global__ void scan_kernel() {
    const int* cnt; int* off; int n;
    if (blockIdx.x == 0) { cnt = g_cnt_u; off = g_off_u; n = NUM_CU; }
    else                 { cnt = g_cnt_i; off = g_off_i; n = NUM_CI; }

    __shared__ int wsum[32];
    __shared__ int s_carry;
    int tid = threadIdx.x;
    int lane = tid & 31;
    int wid = tid >> 5;
    int nw = blockDim.x >> 5;
    int carry = 0;

    for (int base = 0; base < n; base += blockDim.x) {
        int i = base + tid;
        int v = (i < n) ? cnt[i] : 0;
        int x = v;
        #pragma unroll
        for (int d = 1; d < 32; d <<= 1) {
            int y = __shfl_up_sync(0xffffffffu, x, d);
            if (lane >= d) x += y;
        }
        if (lane == 31) wsum[wid] = x;
        __syncthreads();
        if (wid == 0) {
            int ws = (lane < nw) ? wsum[lane] : 0;
            int xs = ws;
            #pragma unroll
            for (int d = 1; d < 32; d <<= 1) {
                int y = __shfl_up_sync(0xffffffffu, xs, d);
                if (lane >= d) xs += y;
            }
            wsum[lane] = xs - ws;  // exclusive warp-sum prefix
        }
        __syncthreads();
        int excl = carry + wsum[wid] + (x - v);
        if (i < n) off[i] = excl;
        if (tid == blockDim.x - 1) s_carry = excl + v;
        __syncthreads();
        carry = s_carry;
        __syncthreads();
    }
    if (tid == 0) off[n] = carry;
}

__global__ void bucket_kernel(const int* __restrict__ cu,
                              const int* __restrict__ ci) {
    int e = blockIdx.x * blockDim.x + threadIdx.x;
    if (e >= NUM_EDGES) return;
    int a = cu[e], b = ci[e];
    float nr = g_w[e] * rsqrtf(g_deg_u[a] + EPS) * rsqrtf(g_deg_i[b] + EPS);
    int nb = __float_as_int(nr);
    int pu = g_off_u[a] + atomicAdd(&g_cur_u[a], 1);
    g_bu[pu] = make_int2(b, nb);
    int pi = g_off_i[b] + atomicAdd(&g_cur_i[b], 1);
    g_bi[pi] = make_int2(a, nb);
}

__global__ void init_kernel(const float* __restrict__ user_w,
                            const float* __restrict__ item_w,
                            const float* __restrict__ user_d,
                            const float* __restrict__ item_d,
                            float* __restrict__ out) {
    int i = blockIdx.x * blockDim.x + threadIdx.x;
    const int NU = NUM_CU * DIM;
    const int TOT = (NUM_CU + NUM_CI) * DIM;
    if (i >= TOT) return;
    if (i < NU) {
        float v = user_w[i] + user_d[i];
        g_u[0][i] = v;
        out[i] = v;
    } else {
        int j = i - NU;
        float v = item_w[j] + item_d[j];
        g_it[0][j] = v;
        out[i] = v;
    }
}

// Fused both-direction propagation: warp per node, atomic-free gather-reduce.
__global__ void prop_kernel(int p, float* __restrict__ out) {
    int gw = (blockIdx.x * blockDim.x + threadIdx.x) >> 5;
    int lane = threadIdx.x & 31;
    if (gw >= NUM_CU + NUM_CI) return;

    const int2* __restrict__ bk;
    const float2* __restrict__ src;
    float2* __restrict__ dst;
    float2* __restrict__ op;
    int n, s, t;
    if (gw < NUM_CU) {
        n = gw;
        s = g_off_u[n]; t = g_off_u[n + 1];
        bk = g_bu;
        src = (const float2*)g_it[p];
        dst = (float2*)g_u[p ^ 1];
        op = (float2*)out;
    } else {
        n = gw - NUM_CU;
        s = g_off_i[n]; t = g_off_i[n + 1];
        bk = g_bi;
        src = (const float2*)g_u[p];
        dst = (float2*)g_it[p ^ 1];
        op = (float2*)(out + NUM_CU * DIM);
    }

    float2 acc = make_float2(0.f, 0.f);
    int k = s;
    // 2x unroll for memory-level parallelism
    for (; k + 2 <= t; k += 2) {
        int2 e0 = __ldg(&bk[k]);
        int2 e1 = __ldg(&bk[k + 1]);
        float2 v0 = __ldg(&src[e0.x * 32 + lane]);
        float2 v1 = __ldg(&src[e1.x * 32 + lane]);
        float n0 = __int_as_float(e0.y);
        float n1 = __int_as_float(e1.y);
        acc.x = fmaf(n0, v0.x, acc.x);
        acc.y = fmaf(n0, v0.y, acc.y);
        acc.x = fmaf(n1, v1.x, acc.x);
        acc.y = fmaf(n1, v1.y, acc.y);
    }
    if (k < t) {
        int2 e0 = __ldg(&bk[k]);
        float2 v0 = __ldg(&src[e0.x * 32 + lane]);
        float n0 = __int_as_float(e0.y);
        acc.x = fmaf(n0, v0.x, acc.x);
        acc.y = fmaf(n0, v0.y, acc.y);
    }

    int idx = n * 32 + lane;
    dst[idx] = acc;
    float2 cur = op[idx];
    cur.x += acc.x;
    cur.y += acc.y;
    op[idx] = cur;
}

__global__ void scale_kernel(float* __restrict__ out) {
    int i = blockIdx.x * blockDim.x + threadIdx.x;
    const int TOT = (NUM_CU + NUM_CI) * DIM;
    if (i >= TOT) return;
    out[i] *= (1.0f / (NUM_LAYERS + 1));
}

// ---------------- launch ----------------
extern "C" void kernel_launch(void* const* d_in, const int* in_sizes, int n_in,
                              void* d_out, int out_size) {
    const float* user_w     = (const float*)d_in[0];
    const float* item_w     = (const float*)d_in[1];
    const float* user_delta = (const float*)d_in[2];
    const float* item_delta = (const float*)d_in[3];
    const float* edge_logit = (const float*)d_in[4];
    const int*   cu         = (const int*)d_in[5];
    const int*   ci         = (const int*)d_in[6];
    float* out = (float*)d_out;

    const int BT = 256;
    int gEdges = (NUM_EDGES + BT - 1) / BT;
    int gNodes = (NUM_CU + BT - 1) / BT;
    int gTot   = ((NUM_CU + NUM_CI) * DIM + BT - 1) / BT;
    int gProp  = ((NUM_CU + NUM_CI) * 32 + BT - 1) / BT;

    zero_kernel<<<gNodes, BT>>>();
    edge_w_kernel<<<gEdges, BT>>>(edge_logit, cu, ci);
    scan_kernel<<<2, 1024>>>();
    bucket_kernel<<<gEdges, BT>>>(cu, ci);
    init_kernel<<<gTot, BT>>>(user_w, item_w, user_delta, item_delta, out);

    int p = 0;
    for (int L = 0; L < NUM_LAYERS; ++L) {
        prop_kernel<<<gProp, BT>>>(p, out);
        p ^= 1;
    }
    scale_kernel<<<gTot, BT>>>(out);
}

// round 2
// speedup vs baseline: 1.3854x; 1.3854x over previous
#include <cuda_runtime.h>

#define NUM_CU 100000
#define NUM_CI 50000
#define DIM 64
#define NUM_LAYERS 3
#define NUM_EDGES 1600000
#define EPS 1e-8f

#define TILE 1024
#define NT_U ((NUM_CU + TILE - 1) / TILE)   // 98
#define NT_I ((NUM_CI + TILE - 1) / TILE)   // 49

// ---------------- scratch (device globals; no allocation allowed) ----------------
__device__ float g_w[NUM_EDGES];
__device__ float g_deg_u[NUM_CU];
__device__ float g_deg_i[NUM_CI];
__device__ int   g_cnt_u[NUM_CU];
__device__ int   g_cnt_i[NUM_CI];
__device__ int   g_cur_u[NUM_CU];
__device__ int   g_cur_i[NUM_CI];
__device__ int   g_off_u[NUM_CU + 1];
__device__ int   g_off_i[NUM_CI + 1];
__device__ int   g_part[NT_U + NT_I];
__device__ int2  g_bu[NUM_EDGES];                // user buckets: {item_idx, norm bits}
__device__ int2  g_bi[NUM_EDGES];                // item buckets: {user_idx, norm bits}
__device__ __align__(16) float g_u[2][NUM_CU * DIM];
__device__ __align__(16) float g_it[2][NUM_CI * DIM];

// ---------------- kernels ----------------

__global__ void zero_kernel() {
    int i = blockIdx.x * blockDim.x + threadIdx.x;
    if (i < NUM_CU) { g_deg_u[i] = 0.f; g_cnt_u[i] = 0; g_cur_u[i] = 0; }
    if (i < NUM_CI) { g_deg_i[i] = 0.f; g_cnt_i[i] = 0; g_cur_i[i] = 0; }
}

__global__ void edge_w_kernel(const float* __restrict__ logit,
                              const int* __restrict__ cu,
                              const int* __restrict__ ci) {
    int e = blockIdx.x * blockDim.x + threadIdx.x;
    if (e >= NUM_EDGES) return;
    float x = logit[e];
    float w = (x > 0.f ? x + log1pf(expf(-x)) : log1pf(expf(x))) + EPS;
    g_w[e] = w;
    int a = cu[e], b = ci[e];
    atomicAdd(&g_deg_u[a], w);
    atomicAdd(&g_deg_i[b], w);
    atomicAdd(&g_cnt_u[a], 1);
    atomicAdd(&g_cnt_i[b], 1);
}

// Phase A: per-tile sums (grid = NT_U + NT_I blocks of 1024)
__global__ void scanA_kernel() {
    int b = blockIdx.x;
    const int* cnt; int n; int tile;
    if (b < NT_U) { cnt = g_cnt_u; n = NUM_CU; tile = b; }
    else          { cnt = g_cnt_i; n = NUM_CI; tile = b - NT_U; }
    int i = tile * TILE + threadIdx.x;
    int v = (i < n) ? cnt[i] : 0;
    __shared__ int ws[32];
    int lane = threadIdx.x & 31, wid = threadIdx.x >> 5;
    #pragma unroll
    for (int d = 16; d > 0; d >>= 1) v += __shfl_down_sync(0xffffffffu, v, d);
    if (lane == 0) ws[wid] = v;
    __syncthreads();
    if (wid == 0) {
        int s = ws[lane];
        #pragma unroll
        for (int d = 16; d > 0; d >>= 1) s += __shfl_down_sync(0xffffffffu, s, d);
        if (lane == 0) g_part[b] = s;
    }
}

// Phase B: exclusive-scan the tile sums. Warp 0: users, warp 1: items.
__global__ void scanB_kernel() {
    int wid = threadIdx.x >> 5;
    int lane = threadIdx.x & 31;
    int base, cntT, total_slot;
    if (wid == 0) { base = 0;    cntT = NT_U; }
    else if (wid == 1) { base = NT_U; cntT = NT_I; }
    else return;
    int carry = 0;
    for (int s = 0; s < cntT; s += 32) {
        int i = s + lane;
        int v = (i < cntT) ? g_part[base + i] : 0;
        int x = v;
        #pragma unroll
        for (int d = 1; d < 32; d <<= 1) {
            int y = __shfl_up_sync(0xffffffffu, x, d);
            if (lane >= d) x += y;
        }
        if (i < cntT) g_part[base + i] = carry + x - v;   // exclusive
        carry += __shfl_sync(0xffffffffu, x, 31);
    }
    if (lane == 0) {
        if (wid == 0) g_off_u[NUM_CU] = carry;
        else          g_off_i[NUM_CI] = carry;
    }
}

// Phase C: exclusive scan within each tile + tile base → offsets
__global__ void scanC_kernel() {
    int b = blockIdx.x;
    const int* cnt; int* off; int n; int tile;
    if (b < NT_U) { cnt = g_cnt_u; off = g_off_u; n = NUM_CU; tile = b; }
    else          { cnt = g_cnt_i; off = g_off_i; n = NUM_CI; tile = b - NT_U; }
    int i = tile * TILE + threadIdx.x;
    int v = (i < n) ? cnt[i] : 0;
    int lane = threadIdx.x & 31, wid = threadIdx.x >> 5;
    __shared__ int ws[32];
    int x = v;
    #pragma unroll
    for (int d = 1; d < 32; d <<= 1) {
        int y = __shfl_up_sync(0xffffffffu, x, d);
        if (lane >= d) x += y;
    }
    if (lane == 31) ws[wid] = x;
    __syncthreads();
    if (wid == 0) {
        int wv = ws[lane];
        int xs = wv;
        #pragma unroll
        for (int d = 1; d < 32; d <<= 1) {
            int y = __shfl_up_sync(0xffffffffu, xs, d);
            if (lane >= d) xs += y;
        }
        ws[lane] = xs - wv;
    }
    __syncthreads();
    if (i < n) off[i] = g_part[b] + ws[wid] + (x - v);
}

__global__ void bucket_kernel(const int* __restrict__ cu,
                              const int* __restrict__ ci) {
    int e = blockIdx.x * blockDim.x + threadIdx.x;
    if (e >= NUM_EDGES) return;
    int a = cu[e], b = ci[e];
    float nr = g_w[e] * rsqrtf(g_deg_u[a] + EPS) * rsqrtf(g_deg_i[b] + EPS);
    int nb = __float_as_int(nr);
    int pu = g_off_u[a] + atomicAdd(&g_cur_u[a], 1);
    g_bu[pu] = make_int2(b, nb);
    int pi = g_off_i[b] + atomicAdd(&g_cur_i[b], 1);
    g_bi[pi] = make_int2(a, nb);
}

__global__ void init_kernel(const float* __restrict__ user_w,
                            const float* __restrict__ item_w,
                            const float* __restrict__ user_d,
                            const float* __restrict__ item_d,
                            float* __restrict__ out) {
    int i = blockIdx.x * blockDim.x + threadIdx.x;
    const int NU = NUM_CU * DIM;
    const int TOT = (NUM_CU + NUM_CI) * DIM;
    if (i >= TOT) return;
    if (i < NU) {
        float v = user_w[i] + user_d[i];
        g_u[0][i] = v;
        out[i] = v;
    } else {
        int j = i - NU;
        float v = item_w[j] + item_d[j];
        g_it[0][j] = v;
        out[i] = v;
    }
}

// Fused both-direction propagation: warp per node, atomic-free gather-reduce.
template <bool LAST>
__global__ __launch_bounds__(256) void prop_kernel(int p, float* __restrict__ out) {
    int gw = (blockIdx.x * blockDim.x + threadIdx.x) >> 5;
    int lane = threadIdx.x & 31;
    if (gw >= NUM_CU + NUM_CI) return;

    const int2* __restrict__ bk;
    const float2* __restrict__ src;
    float2* __restrict__ dst;
    float2* __restrict__ op;
    int n, s, t;
    if (gw < NUM_CU) {
        n = gw;
        s = g_off_u[n]; t = g_off_u[n + 1];
        bk = g_bu;
        src = (const float2*)g_it[p];
        dst = (float2*)g_u[p ^ 1];
        op = (float2*)out;
    } else {
        n = gw - NUM_CU;
        s = g_off_i[n]; t = g_off_i[n + 1];
        bk = g_bi;
        src = (const float2*)g_u[p];
        dst = (float2*)g_it[p ^ 1];
        op = (float2*)(out + NUM_CU * DIM);
    }

    float2 acc = make_float2(0.f, 0.f);
    int k = s;
    for (; k + 4 <= t; k += 4) {
        int2 e0 = __ldg(&bk[k]);
        int2 e1 = __ldg(&bk[k + 1]);
        int2 e2 = __ldg(&bk[k + 2]);
        int2 e3 = __ldg(&bk[k + 3]);
        float2 v0 = __ldg(&src[e0.x * 32 + lane]);
        float2 v1 = __ldg(&src[e1.x * 32 + lane]);
        float2 v2 = __ldg(&src[e2.x * 32 + lane]);
        float2 v3 = __ldg(&src[e3.x * 32 + lane]);
        float n0 = __int_as_float(e0.y), n1 = __int_as_float(e1.y);
        float n2 = __int_as_float(e2.y), n3 = __int_as_float(e3.y);
        acc.x = fmaf(n0, v0.x, acc.x);  acc.y = fmaf(n0, v0.y, acc.y);
        acc.x = fmaf(n1, v1.x, acc.x);  acc.y = fmaf(n1, v1.y, acc.y);
        acc.x = fmaf(n2, v2.x, acc.x);  acc.y = fmaf(n2, v2.y, acc.y);
        acc.x = fmaf(n3, v3.x, acc.x);  acc.y = fmaf(n3, v3.y, acc.y);
    }
    for (; k < t; ++k) {
        int2 e0 = __ldg(&bk[k]);
        float2 v0 = __ldg(&src[e0.x * 32 + lane]);
        float n0 = __int_as_float(e0.y);
        acc.x = fmaf(n0, v0.x, acc.x);
        acc.y = fmaf(n0, v0.y, acc.y);
    }

    int idx = n * 32 + lane;
    float2 cur = op[idx];
    if (LAST) {
        const float sc = 1.0f / (NUM_LAYERS + 1);
        cur.x = (cur.x + acc.x) * sc;
        cur.y = (cur.y + acc.y) * sc;
        op[idx] = cur;
        // u3/i3 never read again: skip dst write
    } else {
        dst[idx] = acc;
        cur.x += acc.x;
        cur.y += acc.y;
        op[idx] = cur;
    }
}

// ---------------- launch ----------------
extern "C" void kernel_launch(void* const* d_in, const int* in_sizes, int n_in,
                              void* d_out, int out_size) {
    const float* user_w     = (const float*)d_in[0];
    const float* item_w     = (const float*)d_in[1];
    const float* user_delta = (const float*)d_in[2];
    const float* item_delta = (const float*)d_in[3];
    const float* edge_logit = (const float*)d_in[4];
    const int*   cu         = (const int*)d_in[5];
    const int*   ci         = (const int*)d_in[6];
    float* out = (float*)d_out;

    const int BT = 256;
    int gEdges = (NUM_EDGES + BT - 1) / BT;
    int gNodes = (NUM_CU + BT - 1) / BT;
    int gTot   = ((NUM_CU + NUM_CI) * DIM + BT - 1) / BT;
    int gProp  = ((NUM_CU + NUM_CI) * 32 + BT - 1) / BT;

    zero_kernel<<<gNodes, BT>>>();
    edge_w_kernel<<<gEdges, BT>>>(edge_logit, cu, ci);
    scanA_kernel<<<NT_U + NT_I, TILE>>>();
    scanB_kernel<<<1, 64>>>();
    scanC_kernel<<<NT_U + NT_I, TILE>>>();
    bucket_kernel<<<gEdges, BT>>>(cu, ci);
    init_kernel<<<gTot, BT>>>(user_w, item_w, user_delta, item_delta, out);

    prop_kernel<false><<<gProp, BT>>>(0, out);
    prop_kernel<false><<<gProp, BT>>>(1, out);
    prop_kernel<true ><<<gProp, BT>>>(0, out);
}

// round 3
// speedup vs baseline: 1.5177x; 1.0955x over previous
#include <cuda_runtime.h>
#include <cuda_fp16.h>

#define NUM_CU 100000
#define NUM_CI 50000
#define DIM 64
#define NUM_LAYERS 3
#define NUM_EDGES 1600000
#define EPS 1e-8f

#define TILE 1024
#define NT_U ((NUM_CU + TILE - 1) / TILE)   // 98
#define NT_I ((NUM_CI + TILE - 1) / TILE)   // 49

// ---------------- scratch (device globals; no allocation allowed) ----------------
__device__ float g_w[NUM_EDGES];
__device__ int   g_rank_u[NUM_EDGES];
__device__ int   g_rank_i[NUM_EDGES];
__device__ float g_deg_u[NUM_CU];
__device__ float g_deg_i[NUM_CI];
__device__ int   g_cnt_u[NUM_CU];
__device__ int   g_cnt_i[NUM_CI];
__device__ int   g_off_u[NUM_CU + 1];
__device__ int   g_off_i[NUM_CI + 1];
__device__ int   g_part[NT_U + NT_I];
__device__ int2  g_bu[NUM_EDGES];                // user buckets: {item_idx, norm bits}
__device__ int2  g_bi[NUM_EDGES];                // item buckets: {user_idx, norm bits}
// fp16 ping-pong embeddings: 32 half2 per node (=64 dims, 128 B)
__device__ __align__(16) __half2 g_uh[2][NUM_CU * 32];
__device__ __align__(16) __half2 g_ih[2][NUM_CI * 32];

// ---------------- kernels ----------------

__global__ void zero_kernel() {
    int i = blockIdx.x * blockDim.x + threadIdx.x;
    if (i < NUM_CU) { g_deg_u[i] = 0.f; g_cnt_u[i] = 0; }
    if (i < NUM_CI) { g_deg_i[i] = 0.f; g_cnt_i[i] = 0; }
}

__global__ void edge_w_kernel(const float* __restrict__ logit,
                              const int* __restrict__ cu,
                              const int* __restrict__ ci) {
    int e = blockIdx.x * blockDim.x + threadIdx.x;
    if (e >= NUM_EDGES) return;
    float x = logit[e];
    float w = (x > 0.f ? x + log1pf(expf(-x)) : log1pf(expf(x))) + EPS;
    g_w[e] = w;
    int a = cu[e], b = ci[e];
    atomicAdd(&g_deg_u[a], w);
    atomicAdd(&g_deg_i[b], w);
    g_rank_u[e] = atomicAdd(&g_cnt_u[a], 1);   // rank doubles as bucket slot
    g_rank_i[e] = atomicAdd(&g_cnt_i[b], 1);
}

// Phase A: per-tile sums
__global__ void scanA_kernel() {
    int b = blockIdx.x;
    const int* cnt; int n; int tile;
    if (b < NT_U) { cnt = g_cnt_u; n = NUM_CU; tile = b; }
    else          { cnt = g_cnt_i; n = NUM_CI; tile = b - NT_U; }
    int i = tile * TILE + threadIdx.x;
    int v = (i < n) ? cnt[i] : 0;
    __shared__ int ws[32];
    int lane = threadIdx.x & 31, wid = threadIdx.x >> 5;
    #pragma unroll
    for (int d = 16; d > 0; d >>= 1) v += __shfl_down_sync(0xffffffffu, v, d);
    if (lane == 0) ws[wid] = v;
    __syncthreads();
    if (wid == 0) {
        int s = ws[lane];
        #pragma unroll
        for (int d = 16; d > 0; d >>= 1) s += __shfl_down_sync(0xffffffffu, s, d);
        if (lane == 0) g_part[b] = s;
    }
}

// Phase B: exclusive-scan tile sums. Warp 0: users, warp 1: items.
__global__ void scanB_kernel() {
    int wid = threadIdx.x >> 5;
    int lane = threadIdx.x & 31;
    int base, cntT;
    if (wid == 0) { base = 0;    cntT = NT_U; }
    else if (wid == 1) { base = NT_U; cntT = NT_I; }
    else return;
    int carry = 0;
    for (int s = 0; s < cntT; s += 32) {
        int i = s + lane;
        int v = (i < cntT) ? g_part[base + i] : 0;
        int x = v;
        #pragma unroll
        for (int d = 1; d < 32; d <<= 1) {
            int y = __shfl_up_sync(0xffffffffu, x, d);
            if (lane >= d) x += y;
        }
        if (i < cntT) g_part[base + i] = carry + x - v;
        carry += __shfl_sync(0xffffffffu, x, 31);
    }
    if (lane == 0) {
        if (wid == 0) g_off_u[NUM_CU] = carry;
        else          g_off_i[NUM_CI] = carry;
    }
}

// Phase C: in-tile exclusive scan + tile base → offsets
__global__ void scanC_kernel() {
    int b = blockIdx.x;
    const int* cnt; int* off; int n; int tile;
    if (b < NT_U) { cnt = g_cnt_u; off = g_off_u; n = NUM_CU; tile = b; }
    else          { cnt = g_cnt_i; off = g_off_i; n = NUM_CI; tile = b - NT_U; }
    int i = tile * TILE + threadIdx.x;
    int v = (i < n) ? cnt[i] : 0;
    int lane = threadIdx.x & 31, wid = threadIdx.x >> 5;
    __shared__ int ws[32];
    int x = v;
    #pragma unroll
    for (int d = 1; d < 32; d <<= 1) {
        int y = __shfl_up_sync(0xffffffffu, x, d);
        if (lane >= d) x += y;
    }
    if (lane == 31) ws[wid] = x;
    __syncthreads();
    if (wid == 0) {
        int wv = ws[lane];
        int xs = wv;
        #pragma unroll
        for (int d = 1; d < 32; d <<= 1) {
            int y = __shfl_up_sync(0xffffffffu, xs, d);
            if (lane >= d) xs += y;
        }
        ws[lane] = xs - wv;
    }
    __syncthreads();
    if (i < n) off[i] = g_part[b] + ws[wid] + (x - v);
}

// Atomic-free bucket scatter using precomputed ranks.
__global__ void bucket_kernel(const int* __restrict__ cu,
                              const int* __restrict__ ci) {
    int e = blockIdx.x * blockDim.x + threadIdx.x;
    if (e >= NUM_EDGES) return;
    int a = cu[e], b = ci[e];
    float nr = g_w[e] * rsqrtf(g_deg_u[a] + EPS) * rsqrtf(g_deg_i[b] + EPS);
    int nb = __float_as_int(nr);
    g_bu[g_off_u[a] + g_rank_u[e]] = make_int2(b, nb);
    g_bi[g_off_i[b] + g_rank_i[e]] = make_int2(a, nb);
}

__global__ void init_kernel(const float* __restrict__ user_w,
                            const float* __restrict__ item_w,
                            const float* __restrict__ user_d,
                            const float* __restrict__ item_d,
                            float* __restrict__ out) {
    int i = blockIdx.x * blockDim.x + threadIdx.x;   // half2-granular index
    const int NU2 = NUM_CU * 32;
    const int TOT2 = (NUM_CU + NUM_CI) * 32;
    if (i >= TOT2) return;
    if (i < NU2) {
        float2 w = ((const float2*)user_w)[i];
        float2 d = ((const float2*)user_d)[i];
        float2 v = make_float2(w.x + d.x, w.y + d.y);
        g_uh[0][i] = __float22half2_rn(v);
        ((float2*)out)[i] = v;
    } else {
        int j = i - NU2;
        float2 w = ((const float2*)item_w)[j];
        float2 d = ((const float2*)item_d)[j];
        float2 v = make_float2(w.x + d.x, w.y + d.y);
        g_ih[0][j] = __float22half2_rn(v);
        ((float2*)out)[i] = v;
    }
}

// Fused both-direction propagation: warp per node, fp16 gather, fp32 accumulate.
template <bool LAST>
__global__ __launch_bounds__(256) void prop_kernel(int p, float* __restrict__ out) {
    int gw = (blockIdx.x * blockDim.x + threadIdx.x) >> 5;
    int lane = threadIdx.x & 31;
    if (gw >= NUM_CU + NUM_CI) return;

    const int2* __restrict__ bk;
    const __half2* __restrict__ src;
    __half2* __restrict__ dst;
    float2* __restrict__ op;
    int n, s, t;
    if (gw < NUM_CU) {
        n = gw;
        s = g_off_u[n]; t = g_off_u[n + 1];
        bk = g_bu;
        src = g_ih[p];
        dst = g_uh[p ^ 1];
        op = (float2*)out;
    } else {
        n = gw - NUM_CU;
        s = g_off_i[n]; t = g_off_i[n + 1];
        bk = g_bi;
        src = g_uh[p];
        dst = g_ih[p ^ 1];
        op = (float2*)(out + NUM_CU * DIM);
    }

    float2 acc = make_float2(0.f, 0.f);
    int k = s;
    for (; k + 4 <= t; k += 4) {
        int2 e0 = __ldg(&bk[k]);
        int2 e1 = __ldg(&bk[k + 1]);
        int2 e2 = __ldg(&bk[k + 2]);
        int2 e3 = __ldg(&bk[k + 3]);
        __half2 h0 = __ldg(&src[e0.x * 32 + lane]);
        __half2 h1 = __ldg(&src[e1.x * 32 + lane]);
        __half2 h2 = __ldg(&src[e2.x * 32 + lane]);
        __half2 h3 = __ldg(&src[e3.x * 32 + lane]);
        float2 v0 = __half22float2(h0);
        float2 v1 = __half22float2(h1);
        float2 v2 = __half22float2(h2);
        float2 v3 = __half22float2(h3);
        float n0 = __int_as_float(e0.y), n1 = __int_as_float(e1.y);
        float n2 = __int_as_float(e2.y), n3 = __int_as_float(e3.y);
        acc.x = fmaf(n0, v0.x, acc.x);  acc.y = fmaf(n0, v0.y, acc.y);
        acc.x = fmaf(n1, v1.x, acc.x);  acc.y = fmaf(n1, v1.y, acc.y);
        acc.x = fmaf(n2, v2.x, acc.x);  acc.y = fmaf(n2, v2.y, acc.y);
        acc.x = fmaf(n3, v3.x, acc.x);  acc.y = fmaf(n3, v3.y, acc.y);
    }
    for (; k < t; ++k) {
        int2 e0 = __ldg(&bk[k]);
        float2 v0 = __half22float2(__ldg(&src[e0.x * 32 + lane]));
        float n0 = __int_as_float(e0.y);
        acc.x = fmaf(n0, v0.x, acc.x);
        acc.y = fmaf(n0, v0.y, acc.y);
    }

    int idx = n * 32 + lane;
    float2 cur = op[idx];
    if (LAST) {
        const float sc = 1.0f / (NUM_LAYERS + 1);
        cur.x = (cur.x + acc.x) * sc;
        cur.y = (cur.y + acc.y) * sc;
        op[idx] = cur;
        // last layer's embedding is never gathered again: skip dst write
    } else {
        dst[idx] = __float22half2_rn(acc);
        cur.x += acc.x;
        cur.y += acc.y;
        op[idx] = cur;
    }
}

// ---------------- launch ----------------
extern "C" void kernel_launch(void* const* d_in, const int* in_sizes, int n_in,
                              void* d_out, int out_size) {
    const float* user_w     = (const float*)d_in[0];
    const float* item_w     = (const float*)d_in[1];
    const float* user_delta = (const float*)d_in[2];
    const float* item_delta = (const float*)d_in[3];
    const float* edge_logit = (const float*)d_in[4];
    const int*   cu         = (const int*)d_in[5];
    const int*   ci         = (const int*)d_in[6];
    float* out = (float*)d_out;

    const int BT = 256;
    int gEdges = (NUM_EDGES + BT - 1) / BT;
    int gNodes = (NUM_CU + BT - 1) / BT;
    int gTot2  = ((NUM_CU + NUM_CI) * 32 + BT - 1) / BT;
    int gProp  = ((NUM_CU + NUM_CI) * 32 + BT - 1) / BT;

    zero_kernel<<<gNodes, BT>>>();
    edge_w_kernel<<<gEdges, BT>>>(edge_logit, cu, ci);
    scanA_kernel<<<NT_U + NT_I, TILE>>>();
    scanB_kernel<<<1, 64>>>();
    scanC_kernel<<<NT_U + NT_I, TILE>>>();
    bucket_kernel<<<gEdges, BT>>>(cu, ci);
    init_kernel<<<gTot2, BT>>>(user_w, item_w, user_delta, item_delta, out);

    prop_kernel<false><<<gProp, BT>>>(0, out);
    prop_kernel<false><<<gProp, BT>>>(1, out);
    prop_kernel<true ><<<gProp, BT>>>(0, out);
}

// round 4
// speedup vs baseline: 1.6040x; 1.0568x over previous
#include <cuda_runtime.h>
#include <cuda_fp16.h>

#define NUM_CU 100000
#define NUM_CI 50000
#define DIM 64
#define NUM_LAYERS 3
#define NUM_EDGES 1600000
#define EPS 1e-8f

#define TILE 1024
#define NT_U ((NUM_CU + TILE - 1) / TILE)   // 98
#define NT_I ((NUM_CI + TILE - 1) / TILE)   // 49
#define NT_TOT (NT_U + NT_I)                // 147

// ---------------- scratch (device globals; no allocation allowed) ----------------
__device__ int   g_rank_u[NUM_EDGES];
__device__ int   g_rank_i[NUM_EDGES];
__device__ float g_deg_u[NUM_CU];
__device__ float g_deg_i[NUM_CI];
__device__ int   g_cnt_u[NUM_CU];
__device__ int   g_cnt_i[NUM_CI];
__device__ int   g_off_u[NUM_CU + 1];
__device__ int   g_off_i[NUM_CI + 1];
__device__ int   g_part[NT_TOT];
__device__ int2  g_bu[NUM_EDGES];                // user buckets: {item_idx, norm bits}
__device__ int2  g_bi[NUM_EDGES];                // item buckets: {user_idx, norm bits}
// fp16 ping-pong embeddings: 32 half2 per node (=64 dims, 128 B)
__device__ __align__(16) __half2 g_uh[2][NUM_CU * 32];
__device__ __align__(16) __half2 g_ih[2][NUM_CI * 32];

__device__ __forceinline__ float softplus_eps(float x) {
    return (x > 0.f ? x + log1pf(expf(-x)) : log1pf(expf(x))) + EPS;
}

// ---------------- kernels ----------------

__global__ void zero_kernel() {
    int i = blockIdx.x * blockDim.x + threadIdx.x;
    if (i < NUM_CU) { g_deg_u[i] = 0.f; g_cnt_u[i] = 0; }
    if (i < NUM_CI) { g_deg_i[i] = 0.f; g_cnt_i[i] = 0; }
}

// 2 edges per thread for ILP against atomic latency.
__global__ void edge_w_kernel(const float* __restrict__ logit,
                              const int* __restrict__ cu,
                              const int* __restrict__ ci) {
    int t = blockIdx.x * blockDim.x + threadIdx.x;
    int e0 = t * 2;
    if (e0 >= NUM_EDGES) return;
    float x0 = logit[e0], x1 = logit[e0 + 1];
    int a0 = cu[e0], a1 = cu[e0 + 1];
    int b0 = ci[e0], b1 = ci[e0 + 1];
    float w0 = softplus_eps(x0);
    float w1 = softplus_eps(x1);
    atomicAdd(&g_deg_u[a0], w0);
    atomicAdd(&g_deg_u[a1], w1);
    atomicAdd(&g_deg_i[b0], w0);
    atomicAdd(&g_deg_i[b1], w1);
    int r0 = atomicAdd(&g_cnt_u[a0], 1);
    int r1 = atomicAdd(&g_cnt_u[a1], 1);
    int s0 = atomicAdd(&g_cnt_i[b0], 1);
    int s1 = atomicAdd(&g_cnt_i[b1], 1);
    g_rank_u[e0] = r0;  g_rank_u[e0 + 1] = r1;
    g_rank_i[e0] = s0;  g_rank_i[e0 + 1] = s1;
}

// Phase A: per-tile sums
__global__ void scanA_kernel() {
    int b = blockIdx.x;
    const int* cnt; int n; int tile;
    if (b < NT_U) { cnt = g_cnt_u; n = NUM_CU; tile = b; }
    else          { cnt = g_cnt_i; n = NUM_CI; tile = b - NT_U; }
    int i = tile * TILE + threadIdx.x;
    int v = (i < n) ? cnt[i] : 0;
    __shared__ int ws[32];
    int lane = threadIdx.x & 31, wid = threadIdx.x >> 5;
    #pragma unroll
    for (int d = 16; d > 0; d >>= 1) v += __shfl_down_sync(0xffffffffu, v, d);
    if (lane == 0) ws[wid] = v;
    __syncthreads();
    if (wid == 0) {
        int s = ws[lane];
        #pragma unroll
        for (int d = 16; d > 0; d >>= 1) s += __shfl_down_sync(0xffffffffu, s, d);
        if (lane == 0) g_part[b] = s;
    }
}

// Phase B: one 192-thread block scans all 147 partials in a single round.
// Users occupy part[0..NT_U), items part[NT_U..NT_TOT); the item segment
// must restart its prefix at zero.
__global__ void scanB_kernel() {
    __shared__ int sv[192];
    __shared__ int ws[6];
    int tid = threadIdx.x;
    int lane = tid & 31, wid = tid >> 5;
    int v = (tid < NT_TOT) ? g_part[tid] : 0;
    // segmented: zero contribution carried across the user/item boundary is
    // handled by subtracting the user total from item prefixes afterwards.
    int x = v;
    #pragma unroll
    for (int d = 1; d < 32; d <<= 1) {
        int y = __shfl_up_sync(0xffffffffu, x, d);
        if (lane >= d) x += y;
    }
    if (lane == 31) ws[wid] = x;
    __syncthreads();
    if (tid == 0) {
        int c = 0;
        #pragma unroll
        for (int w = 0; w < 6; ++w) { int t = ws[w]; ws[w] = c; c += t; }
    }
    __syncthreads();
    int incl = ws[wid] + x;          // inclusive prefix over the whole array
    sv[tid] = incl;
    __syncthreads();
    int user_total = sv[NT_U - 1];
    int grand      = sv[NT_TOT - 1];
    if (tid < NT_TOT) {
        int excl = incl - v;
        if (tid >= NT_U) excl -= user_total;   // restart item segment
        g_part[tid] = excl;
    }
    if (tid == 0) {
        g_off_u[NUM_CU] = user_total;
        g_off_i[NUM_CI] = grand - user_total;
    }
}

// Phase C: in-tile exclusive scan + tile base → offsets
__global__ void scanC_kernel() {
    int b = blockIdx.x;
    const int* cnt; int* off; int n; int tile;
    if (b < NT_U) { cnt = g_cnt_u; off = g_off_u; n = NUM_CU; tile = b; }
    else          { cnt = g_cnt_i; off = g_off_i; n = NUM_CI; tile = b - NT_U; }
    int i = tile * TILE + threadIdx.x;
    int v = (i < n) ? cnt[i] : 0;
    int lane = threadIdx.x & 31, wid = threadIdx.x >> 5;
    __shared__ int ws[32];
    int x = v;
    #pragma unroll
    for (int d = 1; d < 32; d <<= 1) {
        int y = __shfl_up_sync(0xffffffffu, x, d);
        if (lane >= d) x += y;
    }
    if (lane == 31) ws[wid] = x;
    __syncthreads();
    if (wid == 0) {
        int wv = ws[lane];
        int xs = wv;
        #pragma unroll
        for (int d = 1; d < 32; d <<= 1) {
            int y = __shfl_up_sync(0xffffffffu, xs, d);
            if (lane >= d) xs += y;
        }
        ws[lane] = xs - wv;
    }
    __syncthreads();
    if (i < n) off[i] = g_part[b] + ws[wid] + (x - v);
}

// Atomic-free bucket scatter using precomputed ranks; recompute softplus.
__global__ void bucket_kernel(const float* __restrict__ logit,
                              const int* __restrict__ cu,
                              const int* __restrict__ ci) {
    int e = blockIdx.x * blockDim.x + threadIdx.x;
    if (e >= NUM_EDGES) return;
    int a = cu[e], b = ci[e];
    float w = softplus_eps(logit[e]);
    float nr = w * rsqrtf(g_deg_u[a] + EPS) * rsqrtf(g_deg_i[b] + EPS);
    int nb = __float_as_int(nr);
    g_bu[g_off_u[a] + g_rank_u[e]] = make_int2(b, nb);
    g_bi[g_off_i[b] + g_rank_i[e]] = make_int2(a, nb);
}

__global__ void init_kernel(const float* __restrict__ user_w,
                            const float* __restrict__ item_w,
                            const float* __restrict__ user_d,
                            const float* __restrict__ item_d,
                            float* __restrict__ out) {
    int i = blockIdx.x * blockDim.x + threadIdx.x;   // half2-granular index
    const int NU2 = NUM_CU * 32;
    const int TOT2 = (NUM_CU + NUM_CI) * 32;
    if (i >= TOT2) return;
    if (i < NU2) {
        float2 w = ((const float2*)user_w)[i];
        float2 d = ((const float2*)user_d)[i];
        float2 v = make_float2(w.x + d.x, w.y + d.y);
        g_uh[0][i] = __float22half2_rn(v);
        ((float2*)out)[i] = v;
    } else {
        int j = i - NU2;
        float2 w = ((const float2*)item_w)[j];
        float2 d = ((const float2*)item_d)[j];
        float2 v = make_float2(w.x + d.x, w.y + d.y);
        g_ih[0][j] = __float22half2_rn(v);
        ((float2*)out)[i] = v;
    }
}

// Fused both-direction propagation: warp per node, fp16 gather, fp32 accumulate.
// 8-deep software pipeline: all bucket reads, then all vector loads, then FMAs.
template <bool LAST>
__global__ __launch_bounds__(256) void prop_kernel(int p, float* __restrict__ out) {
    int gw = (blockIdx.x * blockDim.x + threadIdx.x) >> 5;
    int lane = threadIdx.x & 31;
    if (gw >= NUM_CU + NUM_CI) return;

    const int2* __restrict__ bk;
    const __half2* __restrict__ src;
    __half2* __restrict__ dst;
    float2* __restrict__ op;
    int n, s, t;
    if (gw < NUM_CU) {
        n = gw;
        s = g_off_u[n]; t = g_off_u[n + 1];
        bk = g_bu;
        src = g_ih[p];
        dst = g_uh[p ^ 1];
        op = (float2*)out;
    } else {
        n = gw - NUM_CU;
        s = g_off_i[n]; t = g_off_i[n + 1];
        bk = g_bi;
        src = g_uh[p];
        dst = g_ih[p ^ 1];
        op = (float2*)(out + NUM_CU * DIM);
    }

    int idx = n * 32 + lane;
    float2 cur = op[idx];            // hoisted: overlaps with gather loop

    float2 acc = make_float2(0.f, 0.f);
    int k = s;
    for (; k + 8 <= t; k += 8) {
        int2 e[8];
        #pragma unroll
        for (int j = 0; j < 8; ++j) e[j] = __ldg(&bk[k + j]);
        __half2 h[8];
        #pragma unroll
        for (int j = 0; j < 8; ++j) h[j] = __ldg(&src[e[j].x * 32 + lane]);
        #pragma unroll
        for (int j = 0; j < 8; ++j) {
            float2 v = __half22float2(h[j]);
            float nr = __int_as_float(e[j].y);
            acc.x = fmaf(nr, v.x, acc.x);
            acc.y = fmaf(nr, v.y, acc.y);
        }
    }
    if (k + 4 <= t) {
        int2 e[4];
        #pragma unroll
        for (int j = 0; j < 4; ++j) e[j] = __ldg(&bk[k + j]);
        __half2 h[4];
        #pragma unroll
        for (int j = 0; j < 4; ++j) h[j] = __ldg(&src[e[j].x * 32 + lane]);
        #pragma unroll
        for (int j = 0; j < 4; ++j) {
            float2 v = __half22float2(h[j]);
            float nr = __int_as_float(e[j].y);
            acc.x = fmaf(nr, v.x, acc.x);
            acc.y = fmaf(nr, v.y, acc.y);
        }
        k += 4;
    }
    for (; k < t; ++k) {
        int2 e0 = __ldg(&bk[k]);
        float2 v0 = __half22float2(__ldg(&src[e0.x * 32 + lane]));
        float n0 = __int_as_float(e0.y);
        acc.x = fmaf(n0, v0.x, acc.x);
        acc.y = fmaf(n0, v0.y, acc.y);
    }

    if (LAST) {
        const float sc = 1.0f / (NUM_LAYERS + 1);
        cur.x = (cur.x + acc.x) * sc;
        cur.y = (cur.y + acc.y) * sc;
        op[idx] = cur;
        // last layer's embedding is never gathered again: skip dst write
    } else {
        dst[idx] = __float22half2_rn(acc);
        cur.x += acc.x;
        cur.y += acc.y;
        op[idx] = cur;
    }
}

// ---------------- launch ----------------
extern "C" void kernel_launch(void* const* d_in, const int* in_sizes, int n_in,
                              void* d_out, int out_size) {
    const float* user_w     = (const float*)d_in[0];
    const float* item_w     = (const float*)d_in[1];
    const float* user_delta = (const float*)d_in[2];
    const float* item_delta = (const float*)d_in[3];
    const float* edge_logit = (const float*)d_in[4];
    const int*   cu         = (const int*)d_in[5];
    const int*   ci         = (const int*)d_in[6];
    float* out = (float*)d_out;

    const int BT = 256;
    int gEdges  = (NUM_EDGES + BT - 1) / BT;
    int gEdges2 = (NUM_EDGES / 2 + BT - 1) / BT;
    int gNodes  = (NUM_CU + BT - 1) / BT;
    int gTot2   = ((NUM_CU + NUM_CI) * 32 + BT - 1) / BT;
    int gProp   = ((NUM_CU + NUM_CI) * 32 + BT - 1) / BT;

    zero_kernel<<<gNodes, BT>>>();
    edge_w_kernel<<<gEdges2, BT>>>(edge_logit, cu, ci);
    scanA_kernel<<<NT_TOT, TILE>>>();
    scanB_kernel<<<1, 192>>>();
    scanC_kernel<<<NT_TOT, TILE>>>();
    bucket_kernel<<<gEdges, BT>>>(edge_logit, cu, ci);
    init_kernel<<<gTot2, BT>>>(user_w, item_w, user_delta, item_delta, out);

    prop_kernel<false><<<gProp, BT>>>(0, out);
    prop_kernel<false><<<gProp, BT>>>(1, out);
    prop_kernel<true ><<<gProp, BT>>>(0, out);
}

// round 5
// speedup vs baseline: 1.7630x; 1.0991x over previous
#include <cuda_runtime.h>
#include <cuda_fp16.h>

#define NUM_CU 100000
#define NUM_CI 50000
#define DIM 64
#define NUM_LAYERS 3
#define NUM_EDGES 1600000
#define EPS 1e-8f

#define TILE 1024
#define NT_U ((NUM_CU + TILE - 1) / TILE)   // 98
#define NT_I ((NUM_CI + TILE - 1) / TILE)   // 49
#define NT_TOT (NT_U + NT_I)                // 147  (<= 148 SMs: all resident)

// ---------------- scratch (device globals; no allocation allowed) ----------------
__device__ int   g_rank_u[NUM_EDGES];
__device__ int   g_rank_i[NUM_EDGES];
__device__ float g_deg_u[NUM_CU];
__device__ float g_deg_i[NUM_CI];
__device__ int   g_cnt_u[NUM_CU];
__device__ int   g_cnt_i[NUM_CI];
__device__ int   g_off_u[NUM_CU + 1];
__device__ int   g_off_i[NUM_CI + 1];
__device__ int   g_part[NT_TOT];
__device__ int   g_flag[NT_TOT];
__device__ int2  g_bu[NUM_EDGES];                // user buckets: {item_idx, norm bits}
__device__ int2  g_bi[NUM_EDGES];                // item buckets: {user_idx, norm bits}
// fp16 layer embeddings: slot L holds layer-L output (32 half2/node = 128 B)
__device__ __align__(16) __half2 g_uh[3][NUM_CU * 32];
__device__ __align__(16) __half2 g_ih[3][NUM_CI * 32];

__device__ __forceinline__ float softplus_eps(float x) {
    return (x > 0.f ? x + log1pf(expf(-x)) : log1pf(expf(x))) + EPS;
}

// ---------------- kernels ----------------

// Fused: zero counters/flags + layer-0 embedding init (fp16 slot 0 only).
__global__ void init_zero_kernel(const float* __restrict__ user_w,
                                 const float* __restrict__ item_w,
                                 const float* __restrict__ user_d,
                                 const float* __restrict__ item_d) {
    int i = blockIdx.x * blockDim.x + threadIdx.x;
    if (i < NUM_CU) { g_deg_u[i] = 0.f; g_cnt_u[i] = 0; }
    if (i < NUM_CI) { g_deg_i[i] = 0.f; g_cnt_i[i] = 0; }
    if (i < NT_TOT) g_flag[i] = 0;
    const int NU2 = NUM_CU * 32;
    const int TOT2 = (NUM_CU + NUM_CI) * 32;
    if (i >= TOT2) return;
    if (i < NU2) {
        float2 w = ((const float2*)user_w)[i];
        float2 d = ((const float2*)user_d)[i];
        g_uh[0][i] = __float22half2_rn(make_float2(w.x + d.x, w.y + d.y));
    } else {
        int j = i - NU2;
        float2 w = ((const float2*)item_w)[j];
        float2 d = ((const float2*)item_d)[j];
        g_ih[0][j] = __float22half2_rn(make_float2(w.x + d.x, w.y + d.y));
    }
}

// 2 edges per thread for ILP against atomic latency.
__global__ void edge_w_kernel(const float* __restrict__ logit,
                              const int* __restrict__ cu,
                              const int* __restrict__ ci) {
    int t = blockIdx.x * blockDim.x + threadIdx.x;
    int e0 = t * 2;
    if (e0 >= NUM_EDGES) return;
    float x0 = logit[e0], x1 = logit[e0 + 1];
    int a0 = cu[e0], a1 = cu[e0 + 1];
    int b0 = ci[e0], b1 = ci[e0 + 1];
    float w0 = softplus_eps(x0);
    float w1 = softplus_eps(x1);
    atomicAdd(&g_deg_u[a0], w0);
    atomicAdd(&g_deg_u[a1], w1);
    atomicAdd(&g_deg_i[b0], w0);
    atomicAdd(&g_deg_i[b1], w1);
    int r0 = atomicAdd(&g_cnt_u[a0], 1);
    int r1 = atomicAdd(&g_cnt_u[a1], 1);
    int s0 = atomicAdd(&g_cnt_i[b0], 1);
    int s1 = atomicAdd(&g_cnt_i[b1], 1);
    g_rank_u[e0] = r0;  g_rank_u[e0 + 1] = r1;
    g_rank_i[e0] = s0;  g_rank_i[e0 + 1] = s1;
}

// Single-kernel segmented exclusive scan with decoupled lookback.
// 147 blocks of 1024 — all resident simultaneously, so spinning is safe.
__global__ __launch_bounds__(TILE) void scan_kernel() {
    int b = blockIdx.x;
    const int* cnt; int* off; int n; int tile; int segStart;
    if (b < NT_U) { cnt = g_cnt_u; off = g_off_u; n = NUM_CU; tile = b;        segStart = 0;    }
    else          { cnt = g_cnt_i; off = g_off_i; n = NUM_CI; tile = b - NT_U; segStart = NT_U; }

    int tid = threadIdx.x;
    int lane = tid & 31, wid = tid >> 5;
    int i = tile * TILE + tid;
    int v = (i < n) ? cnt[i] : 0;

    __shared__ int ws[32];
    __shared__ int s_total;
    __shared__ int s_base;

    // block-wide scan
    int x = v;
    #pragma unroll
    for (int d = 1; d < 32; d <<= 1) {
        int y = __shfl_up_sync(0xffffffffu, x, d);
        if (lane >= d) x += y;
    }
    if (lane == 31) ws[wid] = x;
    __syncthreads();
    if (wid == 0) {
        int wv = ws[lane];
        int xs = wv;
        #pragma unroll
        for (int d = 1; d < 32; d <<= 1) {
            int y = __shfl_up_sync(0xffffffffu, xs, d);
            if (lane >= d) xs += y;
        }
        ws[lane] = xs - wv;
        if (lane == 31) s_total = xs;
    }
    __syncthreads();
    int excl_blk = ws[wid] + (x - v);

    // post aggregate ASAP, then lookback over segment predecessors
    if (tid == 0) {
        g_part[b] = s_total;
        __threadfence();
        ((volatile int*)g_flag)[b] = 1;
    }
    if (wid == 0) {
        int np = b - segStart;
        int acc = 0;
        for (int j = lane; j < np; j += 32) {
            while (((volatile int*)g_flag)[segStart + j] == 0) { }
            acc += ((volatile int*)g_part)[segStart + j];
        }
        #pragma unroll
        for (int d = 16; d > 0; d >>= 1) acc += __shfl_down_sync(0xffffffffu, acc, d);
        if (lane == 0) s_base = acc;
    }
    __syncthreads();
    int base = s_base;
    if (i < n) off[i] = base + excl_blk;
    if (tid == 0 && (b == NT_U - 1 || b == NT_TOT - 1)) off[n] = base + s_total;
}

// Atomic-free bucket scatter using precomputed ranks; recompute softplus.
__global__ void bucket_kernel(const float* __restrict__ logit,
                              const int* __restrict__ cu,
                              const int* __restrict__ ci) {
    int e = blockIdx.x * blockDim.x + threadIdx.x;
    if (e >= NUM_EDGES) return;
    int a = cu[e], b = ci[e];
    float w = softplus_eps(logit[e]);
    float nr = w * rsqrtf(g_deg_u[a] + EPS) * rsqrtf(g_deg_i[b] + EPS);
    int nb = __float_as_int(nr);
    g_bu[g_off_u[a] + g_rank_u[e]] = make_int2(b, nb);
    g_bi[g_off_i[b] + g_rank_i[e]] = make_int2(a, nb);
}

// Fused both-direction propagation: warp per node, fp16 gather, fp32 accumulate.
// Layer P reads slot P; non-last writes slot P+1; LAST fuses the final
// (e0+e1+e2+e3)/4 epilogue and is the only writer of `out`.
template <int P, bool LAST>
__global__ __launch_bounds__(256) void prop_kernel(float* __restrict__ out) {
    int gw = (blockIdx.x * blockDim.x + threadIdx.x) >> 5;
    int lane = threadIdx.x & 31;
    if (gw >= NUM_CU + NUM_CI) return;

    const int2* __restrict__ bk;
    const __half2* __restrict__ src;
    __half2* __restrict__ dst;
    const __half2 *l0, *l1, *l2;
    float2* __restrict__ op;
    int n, s, t;
    if (gw < NUM_CU) {
        n = gw;
        s = g_off_u[n]; t = g_off_u[n + 1];
        bk = g_bu;
        src = g_ih[P];
        dst = LAST ? (__half2*)0 : g_uh[P + 1 < 3 ? P + 1 : 0];
        l0 = g_uh[0]; l1 = g_uh[1]; l2 = g_uh[2];
        op = (float2*)out;
    } else {
        n = gw - NUM_CU;
        s = g_off_i[n]; t = g_off_i[n + 1];
        bk = g_bi;
        src = g_uh[P];
        dst = LAST ? (__half2*)0 : g_ih[P + 1 < 3 ? P + 1 : 0];
        l0 = g_ih[0]; l1 = g_ih[1]; l2 = g_ih[2];
        op = (float2*)(out + NUM_CU * DIM);
    }

    int idx = n * 32 + lane;
    __half2 a0, a1, a2;
    if (LAST) {            // hoisted epilogue loads overlap with gather loop
        a0 = l0[idx]; a1 = l1[idx]; a2 = l2[idx];
    }

    float2 acc = make_float2(0.f, 0.f);
    int k = s;
    for (; k + 8 <= t; k += 8) {
        int2 e[8];
        #pragma unroll
        for (int j = 0; j < 8; ++j) e[j] = __ldg(&bk[k + j]);
        __half2 h[8];
        #pragma unroll
        for (int j = 0; j < 8; ++j) h[j] = __ldg(&src[e[j].x * 32 + lane]);
        #pragma unroll
        for (int j = 0; j < 8; ++j) {
            float2 v = __half22float2(h[j]);
            float nr = __int_as_float(e[j].y);
            acc.x = fmaf(nr, v.x, acc.x);
            acc.y = fmaf(nr, v.y, acc.y);
        }
    }
    if (k + 4 <= t) {
        int2 e[4];
        #pragma unroll
        for (int j = 0; j < 4; ++j) e[j] = __ldg(&bk[k + j]);
        __half2 h[4];
        #pragma unroll
        for (int j = 0; j < 4; ++j) h[j] = __ldg(&src[e[j].x * 32 + lane]);
        #pragma unroll
        for (int j = 0; j < 4; ++j) {
            float2 v = __half22float2(h[j]);
            float nr = __int_as_float(e[j].y);
            acc.x = fmaf(nr, v.x, acc.x);
            acc.y = fmaf(nr, v.y, acc.y);
        }
        k += 4;
    }
    for (; k < t; ++k) {
        int2 e0 = __ldg(&bk[k]);
        float2 v0 = __half22float2(__ldg(&src[e0.x * 32 + lane]));
        float n0 = __int_as_float(e0.y);
        acc.x = fmaf(n0, v0.x, acc.x);
        acc.y = fmaf(n0, v0.y, acc.y);
    }

    if (LAST) {
        const float sc = 1.0f / (NUM_LAYERS + 1);
        float2 f0 = __half22float2(a0);
        float2 f1 = __half22float2(a1);
        float2 f2 = __half22float2(a2);
        float2 r;
        r.x = (f0.x + f1.x + f2.x + acc.x) * sc;
        r.y = (f0.y + f1.y + f2.y + acc.y) * sc;
        op[idx] = r;
    } else {
        dst[idx] = __float22half2_rn(acc);
    }
}

// ---------------- launch ----------------
extern "C" void kernel_launch(void* const* d_in, const int* in_sizes, int n_in,
                              void* d_out, int out_size) {
    const float* user_w     = (const float*)d_in[0];
    const float* item_w     = (const float*)d_in[1];
    const float* user_delta = (const float*)d_in[2];
    const float* item_delta = (const float*)d_in[3];
    const float* edge_logit = (const float*)d_in[4];
    const int*   cu         = (const int*)d_in[5];
    const int*   ci         = (const int*)d_in[6];
    float* out = (float*)d_out;

    const int BT = 256;
    int gEdges  = (NUM_EDGES + BT - 1) / BT;
    int gEdges2 = (NUM_EDGES / 2 + BT - 1) / BT;
    int gTot2   = ((NUM_CU + NUM_CI) * 32 + BT - 1) / BT;
    int gProp   = ((NUM_CU + NUM_CI) * 32 + BT - 1) / BT;

    init_zero_kernel<<<gTot2, BT>>>(user_w, item_w, user_delta, item_delta);
    edge_w_kernel<<<gEdges2, BT>>>(edge_logit, cu, ci);
    scan_kernel<<<NT_TOT, TILE>>>();
    bucket_kernel<<<gEdges, BT>>>(edge_logit, cu, ci);

    prop_kernel<0, false><<<gProp, BT>>>(out);
    prop_kernel<1, false><<<gProp, BT>>>(out);
    prop_kernel<2, true ><<<gProp, BT>>>(out);
}

// round 7
// speedup vs baseline: 1.7884x; 1.0144x over previous
#include <cuda_runtime.h>
#include <cuda_fp16.h>

#define NUM_CU 100000
#define NUM_CI 50000
#define DIM 64
#define NUM_LAYERS 3
#define NUM_EDGES 1600000
#define EPS 1e-8f

#define TILE 1024
#define NT_U ((NUM_CU + TILE - 1) / TILE)   // 98
#define NT_I ((NUM_CI + TILE - 1) / TILE)   // 49
#define NT_TOT (NT_U + NT_I)                // 147  (<= 148 SMs: all resident)

#define BT 256
#define G_EDGE2 (NUM_EDGES / 2 / BT)                      // 3125 edge blocks (2 edges/thread)
#define G_INIT4 ((NUM_CU + NUM_CI) * 16 / BT)             // 9375 init blocks (float4 granularity)

// ---------------- scratch (device globals; no allocation allowed) ----------------
__device__ int   g_rank_u[NUM_EDGES];
__device__ int   g_rank_i[NUM_EDGES];
__device__ float g_deg_u[NUM_CU];
__device__ float g_deg_i[NUM_CI];
__device__ int   g_cnt_u[NUM_CU];
__device__ int   g_cnt_i[NUM_CI];
__device__ int   g_off_u[NUM_CU + 1];
__device__ int   g_off_i[NUM_CI + 1];
__device__ int   g_part[NT_TOT];
__device__ int   g_flag[NT_TOT];
__device__ int2  g_bu[NUM_EDGES];                // user buckets: {item_idx, norm bits}
__device__ int2  g_bi[NUM_EDGES];                // item buckets: {user_idx, norm bits}
// fp16 layer embeddings: slot L holds layer-L output (32 half2/node = 128 B)
__device__ __align__(16) __half2 g_uh[3][NUM_CU * 32];
__device__ __align__(16) __half2 g_ih[3][NUM_CI * 32];

__device__ __forceinline__ float softplus_eps(float x) {
    return (x > 0.f ? x + log1pf(expf(-x)) : log1pf(expf(x))) + EPS;
}

__device__ __forceinline__ unsigned h2_bits(__half2 h) {
    __half2_raw r = h;
    return (unsigned)r.x | ((unsigned)r.y << 16);
}

// ---------------- kernels ----------------

// Tiny: zero counters / degree / lookback flags (1.2 MB total).
__global__ void zero_kernel() {
    int i = blockIdx.x * blockDim.x + threadIdx.x;
    if (i < NUM_CU) { g_deg_u[i] = 0.f; g_cnt_u[i] = 0; }
    if (i < NUM_CI) { g_deg_i[i] = 0.f; g_cnt_i[i] = 0; }
    if (i < NT_TOT) g_flag[i] = 0;
}

// Fused: edge blocks (L2-atomic bound) + embedding-init blocks (DRAM bound)
// run concurrently — orthogonal resources.
__global__ void edge_init_kernel(const float* __restrict__ logit,
                                 const int* __restrict__ cu,
                                 const int* __restrict__ ci,
                                 const float* __restrict__ user_w,
                                 const float* __restrict__ item_w,
                                 const float* __restrict__ user_d,
                                 const float* __restrict__ item_d) {
    int b = blockIdx.x;
    if (b < G_EDGE2) {
        // ---- edge part: 2 edges per thread ----
        int e0 = (b * BT + threadIdx.x) * 2;
        float x0 = logit[e0], x1 = logit[e0 + 1];
        int a0 = cu[e0], a1 = cu[e0 + 1];
        int b0 = ci[e0], b1 = ci[e0 + 1];
        float w0 = softplus_eps(x0);
        float w1 = softplus_eps(x1);
        atomicAdd(&g_deg_u[a0], w0);
        atomicAdd(&g_deg_u[a1], w1);
        atomicAdd(&g_deg_i[b0], w0);
        atomicAdd(&g_deg_i[b1], w1);
        int r0 = atomicAdd(&g_cnt_u[a0], 1);
        int r1 = atomicAdd(&g_cnt_u[a1], 1);
        int s0 = atomicAdd(&g_cnt_i[b0], 1);
        int s1 = atomicAdd(&g_cnt_i[b1], 1);
        g_rank_u[e0] = r0;  g_rank_u[e0 + 1] = r1;
        g_rank_i[e0] = s0;  g_rank_i[e0 + 1] = s1;
    } else {
        // ---- init part: float4 granularity (4 floats = 2 half2 per thread) ----
        int i = (b - G_EDGE2) * BT + threadIdx.x;       // float4 index
        const int NU4 = NUM_CU * 16;
        const float4* wsrc; const float4* dsrc; uint2* dst; int j;
        if (i < NU4) {
            wsrc = (const float4*)user_w; dsrc = (const float4*)user_d;
            dst = (uint2*)g_uh[0]; j = i;
        } else {
            wsrc = (const float4*)item_w; dsrc = (const float4*)item_d;
            dst = (uint2*)g_ih[0]; j = i - NU4;
        }
        float4 w = wsrc[j];
        float4 d = dsrc[j];
        __half2 h0 = __float22half2_rn(make_float2(w.x + d.x, w.y + d.y));
        __half2 h1 = __float22half2_rn(make_float2(w.z + d.z, w.w + d.w));
        uint2 pk;
        pk.x = h2_bits(h0);
        pk.y = h2_bits(h1);
        dst[j] = pk;
    }
}

// Single-kernel segmented exclusive scan with decoupled lookback.
// 147 blocks of 1024 — all resident simultaneously, so spinning is safe.
__global__ __launch_bounds__(TILE) void scan_kernel() {
    int b = blockIdx.x;
    const int* cnt; int* off; int n; int tile; int segStart;
    if (b < NT_U) { cnt = g_cnt_u; off = g_off_u; n = NUM_CU; tile = b;        segStart = 0;    }
    else          { cnt = g_cnt_i; off = g_off_i; n = NUM_CI; tile = b - NT_U; segStart = NT_U; }

    int tid = threadIdx.x;
    int lane = tid & 31, wid = tid >> 5;
    int i = tile * TILE + tid;
    int v = (i < n) ? cnt[i] : 0;

    __shared__ int ws[32];
    __shared__ int s_total;
    __shared__ int s_base;

    int x = v;
    #pragma unroll
    for (int d = 1; d < 32; d <<= 1) {
        int y = __shfl_up_sync(0xffffffffu, x, d);
        if (lane >= d) x += y;
    }
    if (lane == 31) ws[wid] = x;
    __syncthreads();
    if (wid == 0) {
        int wv = ws[lane];
        int xs = wv;
        #pragma unroll
        for (int d = 1; d < 32; d <<= 1) {
            int y = __shfl_up_sync(0xffffffffu, xs, d);
            if (lane >= d) xs += y;
        }
        ws[lane] = xs - wv;
        if (lane == 31) s_total = xs;
    }
    __syncthreads();
    int excl_blk = ws[wid] + (x - v);

    if (tid == 0) {
        g_part[b] = s_total;
        __threadfence();
        ((volatile int*)g_flag)[b] = 1;
    }
    if (wid == 0) {
        int np = b - segStart;
        int acc = 0;
        for (int j = lane; j < np; j += 32) {
            while (((volatile int*)g_flag)[segStart + j] == 0) { }
            acc += ((volatile int*)g_part)[segStart + j];
        }
        #pragma unroll
        for (int d = 16; d > 0; d >>= 1) acc += __shfl_down_sync(0xffffffffu, acc, d);
        if (lane == 0) s_base = acc;
    }
    __syncthreads();
    int base = s_base;
    if (i < n) off[i] = base + excl_blk;
    if (tid == 0 && (b == NT_U - 1 || b == NT_TOT - 1)) off[n] = base + s_total;
}

// Atomic-free bucket scatter, 2 edges/thread for store-latency overlap.
__global__ void bucket_kernel(const float* __restrict__ logit,
                              const int* __restrict__ cu,
                              const int* __restrict__ ci) {
    int e0 = (blockIdx.x * blockDim.x + threadIdx.x) * 2;
    if (e0 >= NUM_EDGES) return;
    int a0 = cu[e0], a1 = cu[e0 + 1];
    int b0 = ci[e0], b1 = ci[e0 + 1];
    float w0 = softplus_eps(logit[e0]);
    float w1 = softplus_eps(logit[e0 + 1]);
    float du0 = g_deg_u[a0], du1 = g_deg_u[a1];
    float di0 = g_deg_i[b0], di1 = g_deg_i[b1];
    int ru0 = g_rank_u[e0], ru1 = g_rank_u[e0 + 1];
    int ri0 = g_rank_i[e0], ri1 = g_rank_i[e0 + 1];
    int ou0 = g_off_u[a0],  ou1 = g_off_u[a1];
    int oi0 = g_off_i[b0],  oi1 = g_off_i[b1];
    float nr0 = w0 * rsqrtf(du0 + EPS) * rsqrtf(di0 + EPS);
    float nr1 = w1 * rsqrtf(du1 + EPS) * rsqrtf(di1 + EPS);
    int nb0 = __float_as_int(nr0);
    int nb1 = __float_as_int(nr1);
    g_bu[ou0 + ru0] = make_int2(b0, nb0);
    g_bu[ou1 + ru1] = make_int2(b1, nb1);
    g_bi[oi0 + ri0] = make_int2(a0, nb0);
    g_bi[oi1 + ri1] = make_int2(a1, nb1);
}

// Fused both-direction propagation: warp per node, fp16 gather, fp32 accumulate.
template <int P, bool LAST>
__global__ __launch_bounds__(256) void prop_kernel(float* __restrict__ out) {
    int gw = (blockIdx.x * blockDim.x + threadIdx.x) >> 5;
    int lane = threadIdx.x & 31;
    if (gw >= NUM_CU + NUM_CI) return;

    const int2* __restrict__ bk;
    const __half2* __restrict__ src;
    __half2* __restrict__ dst;
    const __half2 *l0, *l1, *l2;
    float2* __restrict__ op;
    int n, s, t;
    if (gw < NUM_CU) {
        n = gw;
        s = g_off_u[n]; t = g_off_u[n + 1];
        bk = g_bu;
        src = g_ih[P];
        dst = LAST ? (__half2*)0 : g_uh[P + 1 < 3 ? P + 1 : 0];
        l0 = g_uh[0]; l1 = g_uh[1]; l2 = g_uh[2];
        op = (float2*)out;
    } else {
        n = gw - NUM_CU;
        s = g_off_i[n]; t = g_off_i[n + 1];
        bk = g_bi;
        src = g_uh[P];
        dst = LAST ? (__half2*)0 : g_ih[P + 1 < 3 ? P + 1 : 0];
        l0 = g_ih[0]; l1 = g_ih[1]; l2 = g_ih[2];
        op = (float2*)(out + NUM_CU * DIM);
    }

    int idx = n * 32 + lane;
    __half2 a0, a1, a2;
    if (LAST) {
        a0 = l0[idx]; a1 = l1[idx]; a2 = l2[idx];
    }

    float2 acc = make_float2(0.f, 0.f);
    int k = s;
    for (; k + 8 <= t; k += 8) {
        int2 e[8];
        #pragma unroll
        for (int j = 0; j < 8; ++j) e[j] = __ldg(&bk[k + j]);
        __half2 h[8];
        #pragma unroll
        for (int j = 0; j < 8; ++j) h[j] = __ldg(&src[e[j].x * 32 + lane]);
        #pragma unroll
        for (int j = 0; j < 8; ++j) {
            float2 v = __half22float2(h[j]);
            float nr = __int_as_float(e[j].y);
            acc.x = fmaf(nr, v.x, acc.x);
            acc.y = fmaf(nr, v.y, acc.y);
        }
    }
    if (k + 4 <= t) {
        int2 e[4];
        #pragma unroll
        for (int j = 0; j < 4; ++j) e[j] = __ldg(&bk[k + j]);
        __half2 h[4];
        #pragma unroll
        for (int j = 0; j < 4; ++j) h[j] = __ldg(&src[e[j].x * 32 + lane]);
        #pragma unroll
        for (int j = 0; j < 4; ++j) {
            float2 v = __half22float2(h[j]);
            float nr = __int_as_float(e[j].y);
            acc.x = fmaf(nr, v.x, acc.x);
            acc.y = fmaf(nr, v.y, acc.y);
        }
        k += 4;
    }
    for (; k < t; ++k) {
        int2 e0 = __ldg(&bk[k]);
        float2 v0 = __half22float2(__ldg(&src[e0.x * 32 + lane]));
        float n0 = __int_as_float(e0.y);
        acc.x = fmaf(n0, v0.x, acc.x);
        acc.y = fmaf(n0, v0.y, acc.y);
    }

    if (LAST) {
        const float sc = 1.0f / (NUM_LAYERS + 1);
        float2 f0 = __half22float2(a0);
        float2 f1 = __half22float2(a1);
        float2 f2 = __half22float2(a2);
        float2 r;
        r.x = (f0.x + f1.x + f2.x + acc.x) * sc;
        r.y = (f0.y + f1.y + f2.y + acc.y) * sc;
        op[idx] = r;
    } else {
        dst[idx] = __float22half2_rn(acc);
    }
}

// ---------------- launch ----------------
extern "C" void kernel_launch(void* const* d_in, const int* in_sizes, int n_in,
                              void* d_out, int out_size) {
    const float* user_w     = (const float*)d_in[0];
    const float* item_w     = (const float*)d_in[1];
    const float* user_delta = (const float*)d_in[2];
    const float* item_delta = (const float*)d_in[3];
    const float* edge_logit = (const float*)d_in[4];
    const int*   cu         = (const int*)d_in[5];
    const int*   ci         = (const int*)d_in[6];
    float* out = (float*)d_out;

    int gNodes  = (NUM_CU + BT - 1) / BT;
    int gEdges2 = (NUM_EDGES / 2 + BT - 1) / BT;
    int gProp   = ((NUM_CU + NUM_CI) * 32 + BT - 1) / BT;

    zero_kernel<<<gNodes, BT>>>();
    edge_init_kernel<<<G_EDGE2 + G_INIT4, BT>>>(edge_logit, cu, ci,
                                                user_w, item_w, user_delta, item_delta);
    scan_kernel<<<NT_TOT, TILE>>>();
    bucket_kernel<<<gEdges2, BT>>>(edge_logit, cu, ci);

    prop_kernel<0, false><<<gProp, BT>>>(out);
    prop_kernel<1, false><<<gProp, BT>>>(out);
    prop_kernel<2, true ><<<gProp, BT>>>(out);
}

// round 8
// speedup vs baseline: 1.9336x; 1.0812x over previous
#include <cuda_runtime.h>
#include <cuda_fp16.h>

#define NUM_CU 100000
#define NUM_CI 50000
#define DIM 64
#define NUM_LAYERS 3
#define NUM_EDGES 1600000
#define EPS 1e-8f

#define TILE 1024
#define NT_U ((NUM_CU + TILE - 1) / TILE)   // 98
#define NT_I ((NUM_CI + TILE - 1) / TILE)   // 49
#define NT_TOT (NT_U + NT_I)                // 147  (<= 148 SMs: all resident)

#define BT 256
#define G_EDGE2 (NUM_EDGES / 2 / BT)                      // 3125 edge blocks (2 edges/thread)
#define G_INIT4 ((NUM_CU + NUM_CI) * 16 / BT)             // 9375 init blocks (float4 granularity)

#define DEG_SCALE 4294967296.0             // 2^32 fixed-point for packed degree
#define CNT_ONE   (1ull << 48)
#define DEG_MASK  ((1ull << 48) - 1)

// ---------------- scratch (device globals; no allocation allowed) ----------------
__device__ int   g_rank_u[NUM_EDGES];
__device__ int   g_rank_i[NUM_EDGES];
__device__ unsigned long long g_acc_u[NUM_CU];   // [count:16 | deg_fixed:48]
__device__ unsigned long long g_acc_i[NUM_CI];
__device__ int   g_off_u[NUM_CU + 1];
__device__ int   g_off_i[NUM_CI + 1];
__device__ int2  g_meta_u[NUM_CU];               // {bucket offset, rsqrt(deg+EPS) bits}
__device__ int2  g_meta_i[NUM_CI];
__device__ int   g_part[NT_TOT];
__device__ int   g_flag[NT_TOT];
__device__ int2  g_bu[NUM_EDGES];                // user buckets: {item_idx, norm bits}
__device__ int2  g_bi[NUM_EDGES];                // item buckets: {user_idx, norm bits}
// fp16 layer embeddings: slot L holds layer-L output (32 half2/node = 128 B)
__device__ __align__(16) __half2 g_uh[3][NUM_CU * 32];
__device__ __align__(16) __half2 g_ih[3][NUM_CI * 32];

__device__ __forceinline__ float softplus_eps(float x) {
    return (x > 0.f ? x + log1pf(expf(-x)) : log1pf(expf(x))) + EPS;
}

__device__ __forceinline__ unsigned h2_bits(__half2 h) {
    __half2_raw r = h;
    return (unsigned)r.x | ((unsigned)r.y << 16);
}

// ---------------- kernels ----------------

// Tiny: zero packed accumulators / lookback flags.
__global__ void zero_kernel() {
    int i = blockIdx.x * blockDim.x + threadIdx.x;
    if (i < NUM_CU) g_acc_u[i] = 0ull;
    if (i < NUM_CI) g_acc_i[i] = 0ull;
    if (i < NT_TOT) g_flag[i] = 0;
}

// Fused: edge blocks (L2-atomic bound) + embedding-init blocks (DRAM bound)
// run concurrently — orthogonal resources. One u64 atomic per edge per side
// returns rank (high 16 bits) and accumulates fixed-point degree.
__global__ void edge_init_kernel(const float* __restrict__ logit,
                                 const int* __restrict__ cu,
                                 const int* __restrict__ ci,
                                 const float* __restrict__ user_w,
                                 const float* __restrict__ item_w,
                                 const float* __restrict__ user_d,
                                 const float* __restrict__ item_d) {
    int b = blockIdx.x;
    if (b < G_EDGE2) {
        // ---- edge part: 2 edges per thread, 1 packed atomic per side ----
        int e0 = (b * BT + threadIdx.x) * 2;
        float x0 = logit[e0], x1 = logit[e0 + 1];
        int a0 = cu[e0], a1 = cu[e0 + 1];
        int b0 = ci[e0], b1 = ci[e0 + 1];
        float w0 = softplus_eps(x0);
        float w1 = softplus_eps(x1);
        unsigned long long p0 = CNT_ONE | (unsigned long long)((double)w0 * DEG_SCALE);
        unsigned long long p1 = CNT_ONE | (unsigned long long)((double)w1 * DEG_SCALE);
        unsigned long long ru0 = atomicAdd(&g_acc_u[a0], p0);
        unsigned long long ru1 = atomicAdd(&g_acc_u[a1], p1);
        unsigned long long ri0 = atomicAdd(&g_acc_i[b0], p0);
        unsigned long long ri1 = atomicAdd(&g_acc_i[b1], p1);
        g_rank_u[e0]     = (int)(ru0 >> 48);
        g_rank_u[e0 + 1] = (int)(ru1 >> 48);
        g_rank_i[e0]     = (int)(ri0 >> 48);
        g_rank_i[e0 + 1] = (int)(ri1 >> 48);
    } else {
        // ---- init part: float4 granularity (4 floats = 2 half2 per thread) ----
        int i = (b - G_EDGE2) * BT + threadIdx.x;       // float4 index
        const int NU4 = NUM_CU * 16;
        const float4* wsrc; const float4* dsrc; uint2* dst; int j;
        if (i < NU4) {
            wsrc = (const float4*)user_w; dsrc = (const float4*)user_d;
            dst = (uint2*)g_uh[0]; j = i;
        } else {
            wsrc = (const float4*)item_w; dsrc = (const float4*)item_d;
            dst = (uint2*)g_ih[0]; j = i - NU4;
        }
        float4 w = wsrc[j];
        float4 d = dsrc[j];
        __half2 h0 = __float22half2_rn(make_float2(w.x + d.x, w.y + d.y));
        __half2 h1 = __float22half2_rn(make_float2(w.z + d.z, w.w + d.w));
        uint2 pk;
        pk.x = h2_bits(h0);
        pk.y = h2_bits(h1);
        dst[j] = pk;
    }
}

// Single-kernel segmented exclusive scan with decoupled lookback.
// Also emits per-node meta {offset, rsqrt(deg+EPS)} for the bucket pass.
__global__ __launch_bounds__(TILE) void scan_kernel() {
    int b = blockIdx.x;
    const unsigned long long* acc; int* off; int2* meta; int n; int tile; int segStart;
    if (b < NT_U) { acc = g_acc_u; off = g_off_u; meta = g_meta_u; n = NUM_CU; tile = b;        segStart = 0;    }
    else          { acc = g_acc_i; off = g_off_i; meta = g_meta_i; n = NUM_CI; tile = b - NT_U; segStart = NT_U; }

    int tid = threadIdx.x;
    int lane = tid & 31, wid = tid >> 5;
    int i = tile * TILE + tid;
    unsigned long long a = (i < n) ? acc[i] : 0ull;
    int v = (int)(a >> 48);
    float deg = (float)((double)(a & DEG_MASK) * (1.0 / DEG_SCALE));

    __shared__ int ws[32];
    __shared__ int s_total;
    __shared__ int s_base;

    int x = v;
    #pragma unroll
    for (int d = 1; d < 32; d <<= 1) {
        int y = __shfl_up_sync(0xffffffffu, x, d);
        if (lane >= d) x += y;
    }
    if (lane == 31) ws[wid] = x;
    __syncthreads();
    if (wid == 0) {
        int wv = ws[lane];
        int xs = wv;
        #pragma unroll
        for (int d = 1; d < 32; d <<= 1) {
            int y = __shfl_up_sync(0xffffffffu, xs, d);
            if (lane >= d) xs += y;
        }
        ws[lane] = xs - wv;
        if (lane == 31) s_total = xs;
    }
    __syncthreads();
    int excl_blk = ws[wid] + (x - v);

    if (tid == 0) {
        g_part[b] = s_total;
        __threadfence();
        ((volatile int*)g_flag)[b] = 1;
    }
    if (wid == 0) {
        int np = b - segStart;
        int acc2 = 0;
        for (int j = lane; j < np; j += 32) {
            while (((volatile int*)g_flag)[segStart + j] == 0) { }
            acc2 += ((volatile int*)g_part)[segStart + j];
        }
        #pragma unroll
        for (int d = 16; d > 0; d >>= 1) acc2 += __shfl_down_sync(0xffffffffu, acc2, d);
        if (lane == 0) s_base = acc2;
    }
    __syncthreads();
    int base = s_base;
    if (i < n) {
        int o = base + excl_blk;
        off[i] = o;
        meta[i] = make_int2(o, __float_as_int(rsqrtf(deg + EPS)));
    }
    if (tid == 0 && (b == NT_U - 1 || b == NT_TOT - 1)) off[n] = base + s_total;
}

// Atomic-free bucket scatter: per edge, 2 random 8B meta reads + 2 random 8B stores.
__global__ void bucket_kernel(const float* __restrict__ logit,
                              const int* __restrict__ cu,
                              const int* __restrict__ ci) {
    int e = blockIdx.x * blockDim.x + threadIdx.x;
    if (e >= NUM_EDGES) return;
    int a = cu[e], b = ci[e];
    float w = softplus_eps(logit[e]);
    int2 mu = g_meta_u[a];
    int2 mi = g_meta_i[b];
    float nr = w * __int_as_float(mu.y) * __int_as_float(mi.y);
    int nb = __float_as_int(nr);
    g_bu[mu.x + g_rank_u[e]] = make_int2(b, nb);
    g_bi[mi.x + g_rank_i[e]] = make_int2(a, nb);
}

// Fused both-direction propagation: warp per node, fp16 gather, fp32 accumulate.
template <int P, bool LAST>
__global__ __launch_bounds__(256) void prop_kernel(float* __restrict__ out) {
    int gw = (blockIdx.x * blockDim.x + threadIdx.x) >> 5;
    int lane = threadIdx.x & 31;
    if (gw >= NUM_CU + NUM_CI) return;

    const int2* __restrict__ bk;
    const __half2* __restrict__ src;
    __half2* __restrict__ dst;
    const __half2 *l0, *l1, *l2;
    float2* __restrict__ op;
    int n, s, t;
    if (gw < NUM_CU) {
        n = gw;
        s = g_off_u[n]; t = g_off_u[n + 1];
        bk = g_bu;
        src = g_ih[P];
        dst = LAST ? (__half2*)0 : g_uh[P + 1 < 3 ? P + 1 : 0];
        l0 = g_uh[0]; l1 = g_uh[1]; l2 = g_uh[2];
        op = (float2*)out;
    } else {
        n = gw - NUM_CU;
        s = g_off_i[n]; t = g_off_i[n + 1];
        bk = g_bi;
        src = g_uh[P];
        dst = LAST ? (__half2*)0 : g_ih[P + 1 < 3 ? P + 1 : 0];
        l0 = g_ih[0]; l1 = g_ih[1]; l2 = g_ih[2];
        op = (float2*)(out + NUM_CU * DIM);
    }

    int idx = n * 32 + lane;
    __half2 a0, a1, a2;
    if (LAST) {
        a0 = l0[idx]; a1 = l1[idx]; a2 = l2[idx];
    }

    float2 acc = make_float2(0.f, 0.f);
    int k = s;
    for (; k + 8 <= t; k += 8) {
        int2 e[8];
        #pragma unroll
        for (int j = 0; j < 8; ++j) e[j] = __ldg(&bk[k + j]);
        __half2 h[8];
        #pragma unroll
        for (int j = 0; j < 8; ++j) h[j] = __ldg(&src[e[j].x * 32 + lane]);
        #pragma unroll
        for (int j = 0; j < 8; ++j) {
            float2 v = __half22float2(h[j]);
            float nr = __int_as_float(e[j].y);
            acc.x = fmaf(nr, v.x, acc.x);
            acc.y = fmaf(nr, v.y, acc.y);
        }
    }
    if (k + 4 <= t) {
        int2 e[4];
        #pragma unroll
        for (int j = 0; j < 4; ++j) e[j] = __ldg(&bk[k + j]);
        __half2 h[4];
        #pragma unroll
        for (int j = 0; j < 4; ++j) h[j] = __ldg(&src[e[j].x * 32 + lane]);
        #pragma unroll
        for (int j = 0; j < 4; ++j) {
            float2 v = __half22float2(h[j]);
            float nr = __int_as_float(e[j].y);
            acc.x = fmaf(nr, v.x, acc.x);
            acc.y = fmaf(nr, v.y, acc.y);
        }
        k += 4;
    }
    for (; k < t; ++k) {
        int2 e0 = __ldg(&bk[k]);
        float2 v0 = __half22float2(__ldg(&src[e0.x * 32 + lane]));
        float n0 = __int_as_float(e0.y);
        acc.x = fmaf(n0, v0.x, acc.x);
        acc.y = fmaf(n0, v0.y, acc.y);
    }

    if (LAST) {
        const float sc = 1.0f / (NUM_LAYERS + 1);
        float2 f0 = __half22float2(a0);
        float2 f1 = __half22float2(a1);
        float2 f2 = __half22float2(a2);
        float2 r;
        r.x = (f0.x + f1.x + f2.x + acc.x) * sc;
        r.y = (f0.y + f1.y + f2.y + acc.y) * sc;
        op[idx] = r;
    } else {
        dst[idx] = __float22half2_rn(acc);
    }
}

// ---------------- launch ----------------
extern "C" void kernel_launch(void* const* d_in, const int* in_sizes, int n_in,
                              void* d_out, int out_size) {
    const float* user_w     = (const float*)d_in[0];
    const float* item_w     = (const float*)d_in[1];
    const float* user_delta = (const float*)d_in[2];
    const float* item_delta = (const float*)d_in[3];
    const float* edge_logit = (const float*)d_in[4];
    const int*   cu         = (const int*)d_in[5];
    const int*   ci         = (const int*)d_in[6];
    float* out = (float*)d_out;

    int gNodes  = (NUM_CU + BT - 1) / BT;
    int gEdges  = (NUM_EDGES + BT - 1) / BT;
    int gProp   = ((NUM_CU + NUM_CI) * 32 + BT - 1) / BT;

    zero_kernel<<<gNodes, BT>>>();
    edge_init_kernel<<<G_EDGE2 + G_INIT4, BT>>>(edge_logit, cu, ci,
                                                user_w, item_w, user_delta, item_delta);
    scan_kernel<<<NT_TOT, TILE>>>();
    bucket_kernel<<<gEdges, BT>>>(edge_logit, cu, ci);

    prop_kernel<0, false><<<gProp, BT>>>(out);
    prop_kernel<1, false><<<gProp, BT>>>(out);
    prop_kernel<2, true ><<<gProp, BT>>>(out);
}

// round 9
// speedup vs baseline: 1.9501x; 1.0085x over previous
#include <cuda_runtime.h>
#include <cuda_fp16.h>

#define NUM_CU 100000
#define NUM_CI 50000
#define DIM 64
#define NUM_LAYERS 3
#define NUM_EDGES 1600000
#define EPS 1e-8f

#define TILE 1024
#define NT_U ((NUM_CU + TILE - 1) / TILE)   // 98
#define NT_I ((NUM_CI + TILE - 1) / TILE)   // 49
#define NT_TOT (NT_U + NT_I)                // 147  (<= 148 SMs: all resident)

#define BT 256
#define G_EDGE2 (NUM_EDGES / 2 / BT)                      // 3125 edge blocks (2 edges/thread)
#define G_INIT4 ((NUM_CU + NUM_CI) * 16 / BT)             // 9375 init blocks (float4 granularity)
#define G_EI    (G_EDGE2 + G_INIT4)                       // 12500 (=4*G_EDGE2: interleave 1-in-4)

#define DEG_SCALE 4294967296.0             // 2^32 fixed-point for packed degree
#define CNT_ONE   (1ull << 48)
#define DEG_MASK  ((1ull << 48) - 1)

// ---------------- scratch (device globals; no allocation allowed) ----------------
__device__ unsigned g_rank[NUM_EDGES];           // {rank_u:16 | rank_i:16}
__device__ unsigned long long g_acc_u[NUM_CU];   // [count:16 | deg_fixed:48]  (self-zeroed by scan)
__device__ unsigned long long g_acc_i[NUM_CI];
__device__ int   g_off_u[NUM_CU + 1];
__device__ int   g_off_i[NUM_CI + 1];
__device__ int2  g_meta_u[NUM_CU];               // {bucket offset, rsqrt(deg+EPS) bits}
__device__ int2  g_meta_i[NUM_CI];
__device__ int   g_part[NT_TOT];
__device__ int   g_flag[NT_TOT];                 // self-zeroed by bucket
__device__ int2  g_bu[NUM_EDGES];                // user buckets: {item_idx, norm bits}
__device__ int2  g_bi[NUM_EDGES];                // item buckets: {user_idx, norm bits}
// fp16 layer embeddings: slot L holds layer-L output (32 half2/node = 128 B)
__device__ __align__(16) __half2 g_uh[3][NUM_CU * 32];
__device__ __align__(16) __half2 g_ih[3][NUM_CI * 32];

__device__ __forceinline__ float softplus_eps(float x) {
    return (x > 0.f ? x + log1pf(expf(-x)) : log1pf(expf(x))) + EPS;
}

__device__ __forceinline__ unsigned h2_bits(__half2 h) {
    __half2_raw r = h;
    return (unsigned)r.x | ((unsigned)r.y << 16);
}

// ---------------- kernels ----------------

// Fused edge + init kernel; edge blocks interleaved 1-in-4 so the L2-atomic
// stream stays co-resident with the DRAM init stream for the whole kernel.
__global__ void edge_init_kernel(const float* __restrict__ logit,
                                 const int* __restrict__ cu,
                                 const int* __restrict__ ci,
                                 const float* __restrict__ user_w,
                                 const float* __restrict__ item_w,
                                 const float* __restrict__ user_d,
                                 const float* __restrict__ item_d) {
    int b = blockIdx.x;
    if ((b & 3) == 0) {
        // ---- edge part: 2 edges per thread, 1 packed u64 atomic per side ----
        int eb = b >> 2;                                   // 0..G_EDGE2-1
        int e0 = (eb * BT + threadIdx.x) * 2;
        float x0 = logit[e0], x1 = logit[e0 + 1];
        int a0 = cu[e0], a1 = cu[e0 + 1];
        int b0 = ci[e0], b1 = ci[e0 + 1];
        float w0 = softplus_eps(x0);
        float w1 = softplus_eps(x1);
        unsigned long long p0 = CNT_ONE | (unsigned long long)((double)w0 * DEG_SCALE);
        unsigned long long p1 = CNT_ONE | (unsigned long long)((double)w1 * DEG_SCALE);
        unsigned long long ru0 = atomicAdd(&g_acc_u[a0], p0);
        unsigned long long ru1 = atomicAdd(&g_acc_u[a1], p1);
        unsigned long long ri0 = atomicAdd(&g_acc_i[b0], p0);
        unsigned long long ri1 = atomicAdd(&g_acc_i[b1], p1);
        uint2 pk;
        pk.x = (unsigned)(ru0 >> 48) | ((unsigned)(ri0 >> 48) << 16);
        pk.y = (unsigned)(ru1 >> 48) | ((unsigned)(ri1 >> 48) << 16);
        *(uint2*)&g_rank[e0] = pk;
    } else {
        // ---- init part: float4 granularity (4 floats = 2 half2 per thread) ----
        int ib = b - (b >> 2) - 1;                         // 0..G_INIT4-1
        int i = ib * BT + threadIdx.x;                     // float4 index
        const int NU4 = NUM_CU * 16;
        const float4* wsrc; const float4* dsrc; uint2* dst; int j;
        if (i < NU4) {
            wsrc = (const float4*)user_w; dsrc = (const float4*)user_d;
            dst = (uint2*)g_uh[0]; j = i;
        } else {
            wsrc = (const float4*)item_w; dsrc = (const float4*)item_d;
            dst = (uint2*)g_ih[0]; j = i - NU4;
        }
        float4 w = wsrc[j];
        float4 d = dsrc[j];
        __half2 h0 = __float22half2_rn(make_float2(w.x + d.x, w.y + d.y));
        __half2 h1 = __float22half2_rn(make_float2(w.z + d.z, w.w + d.w));
        uint2 pk;
        pk.x = h2_bits(h0);
        pk.y = h2_bits(h1);
        dst[j] = pk;
    }
}

// Single-kernel segmented exclusive scan with decoupled lookback.
// Emits per-node meta {offset, rsqrt(deg+EPS)}; self-zeroes g_acc for the
// next graph replay (consumed exactly once here).
__global__ __launch_bounds__(TILE) void scan_kernel() {
    int b = blockIdx.x;
    unsigned long long* acc; int* off; int2* meta; int n; int tile; int segStart;
    if (b < NT_U) { acc = g_acc_u; off = g_off_u; meta = g_meta_u; n = NUM_CU; tile = b;        segStart = 0;    }
    else          { acc = g_acc_i; off = g_off_i; meta = g_meta_i; n = NUM_CI; tile = b - NT_U; segStart = NT_U; }

    int tid = threadIdx.x;
    int lane = tid & 31, wid = tid >> 5;
    int i = tile * TILE + tid;
    unsigned long long a = 0ull;
    if (i < n) {
        a = acc[i];
        acc[i] = 0ull;                      // self-clean for next replay
    }
    int v = (int)(a >> 48);
    float deg = (float)((double)(a & DEG_MASK) * (1.0 / DEG_SCALE));

    __shared__ int ws[32];
    __shared__ int s_total;
    __shared__ int s_base;

    int x = v;
    #pragma unroll
    for (int d = 1; d < 32; d <<= 1) {
        int y = __shfl_up_sync(0xffffffffu, x, d);
        if (lane >= d) x += y;
    }
    if (lane == 31) ws[wid] = x;
    __syncthreads();
    if (wid == 0) {
        int wv = ws[lane];
        int xs = wv;
        #pragma unroll
        for (int d = 1; d < 32; d <<= 1) {
            int y = __shfl_up_sync(0xffffffffu, xs, d);
            if (lane >= d) xs += y;
        }
        ws[lane] = xs - wv;
        if (lane == 31) s_total = xs;
    }
    __syncthreads();
    int excl_blk = ws[wid] + (x - v);

    if (tid == 0) {
        g_part[b] = s_total;
        __threadfence();
        ((volatile int*)g_flag)[b] = 1;
    }
    if (wid == 0) {
        int np = b - segStart;
        int acc2 = 0;
        for (int j = lane; j < np; j += 32) {
            while (((volatile int*)g_flag)[segStart + j] == 0) { }
            acc2 += ((volatile int*)g_part)[segStart + j];
        }
        #pragma unroll
        for (int d = 16; d > 0; d >>= 1) acc2 += __shfl_down_sync(0xffffffffu, acc2, d);
        if (lane == 0) s_base = acc2;
    }
    __syncthreads();
    int base = s_base;
    if (i < n) {
        int o = base + excl_blk;
        off[i] = o;
        meta[i] = make_int2(o, __float_as_int(rsqrtf(deg + EPS)));
    }
    if (tid == 0 && (b == NT_U - 1 || b == NT_TOT - 1)) off[n] = base + s_total;
}

// Atomic-free bucket scatter: per edge, 2 random 8B meta reads + 2 random 8B
// stores. Block 0 also re-zeroes the scan lookback flags for the next replay.
__global__ void bucket_kernel(const float* __restrict__ logit,
                              const int* __restrict__ cu,
                              const int* __restrict__ ci) {
    if (blockIdx.x == 0 && threadIdx.x < NT_TOT) g_flag[threadIdx.x] = 0;
    int e = blockIdx.x * blockDim.x + threadIdx.x;
    if (e >= NUM_EDGES) return;
    int a = cu[e], b = ci[e];
    float w = softplus_eps(logit[e]);
    unsigned r = g_rank[e];
    int2 mu = g_meta_u[a];
    int2 mi = g_meta_i[b];
    float nr = w * __int_as_float(mu.y) * __int_as_float(mi.y);
    int nb = __float_as_int(nr);
    g_bu[mu.x + (int)(r & 0xFFFFu)] = make_int2(b, nb);
    g_bi[mi.x + (int)(r >> 16)]     = make_int2(a, nb);
}

// Fused both-direction propagation: warp per node, fp16 gather, fp32 accumulate.
template <int P, bool LAST>
__global__ __launch_bounds__(256) void prop_kernel(float* __restrict__ out) {
    int gw = (blockIdx.x * blockDim.x + threadIdx.x) >> 5;
    int lane = threadIdx.x & 31;
    if (gw >= NUM_CU + NUM_CI) return;

    const int2* __restrict__ bk;
    const __half2* __restrict__ src;
    __half2* __restrict__ dst;
    const __half2 *l0, *l1, *l2;
    float2* __restrict__ op;
    int n, s, t;
    if (gw < NUM_CU) {
        n = gw;
        s = g_off_u[n]; t = g_off_u[n + 1];
        bk = g_bu;
        src = g_ih[P];
        dst = LAST ? (__half2*)0 : g_uh[P + 1 < 3 ? P + 1 : 0];
        l0 = g_uh[0]; l1 = g_uh[1]; l2 = g_uh[2];
        op = (float2*)out;
    } else {
        n = gw - NUM_CU;
        s = g_off_i[n]; t = g_off_i[n + 1];
        bk = g_bi;
        src = g_uh[P];
        dst = LAST ? (__half2*)0 : g_ih[P + 1 < 3 ? P + 1 : 0];
        l0 = g_ih[0]; l1 = g_ih[1]; l2 = g_ih[2];
        op = (float2*)(out + NUM_CU * DIM);
    }

    int idx = n * 32 + lane;
    __half2 a0, a1, a2;
    if (LAST) {
        a0 = l0[idx]; a1 = l1[idx]; a2 = l2[idx];
    }

    float2 acc = make_float2(0.f, 0.f);
    int k = s;
    for (; k + 8 <= t; k += 8) {
        int2 e[8];
        #pragma unroll
        for (int j = 0; j < 8; ++j) e[j] = __ldg(&bk[k + j]);
        __half2 h[8];
        #pragma unroll
        for (int j = 0; j < 8; ++j) h[j] = __ldg(&src[e[j].x * 32 + lane]);
        #pragma unroll
        for (int j = 0; j < 8; ++j) {
            float2 v = __half22float2(h[j]);
            float nr = __int_as_float(e[j].y);
            acc.x = fmaf(nr, v.x, acc.x);
            acc.y = fmaf(nr, v.y, acc.y);
        }
    }
    if (k + 4 <= t) {
        int2 e[4];
        #pragma unroll
        for (int j = 0; j < 4; ++j) e[j] = __ldg(&bk[k + j]);
        __half2 h[4];
        #pragma unroll
        for (int j = 0; j < 4; ++j) h[j] = __ldg(&src[e[j].x * 32 + lane]);
        #pragma unroll
        for (int j = 0; j < 4; ++j) {
            float2 v = __half22float2(h[j]);
            float nr = __int_as_float(e[j].y);
            acc.x = fmaf(nr, v.x, acc.x);
            acc.y = fmaf(nr, v.y, acc.y);
        }
        k += 4;
    }
    for (; k < t; ++k) {
        int2 e0 = __ldg(&bk[k]);
        float2 v0 = __half22float2(__ldg(&src[e0.x * 32 + lane]));
        float n0 = __int_as_float(e0.y);
        acc.x = fmaf(n0, v0.x, acc.x);
        acc.y = fmaf(n0, v0.y, acc.y);
    }

    if (LAST) {
        const float sc = 1.0f / (NUM_LAYERS + 1);
        float2 f0 = __half22float2(a0);
        float2 f1 = __half22float2(a1);
        float2 f2 = __half22float2(a2);
        float2 r;
        r.x = (f0.x + f1.x + f2.x + acc.x) * sc;
        r.y = (f0.y + f1.y + f2.y + acc.y) * sc;
        op[idx] = r;
    } else {
        dst[idx] = __float22half2_rn(acc);
    }
}

// ---------------- launch ----------------
extern "C" void kernel_launch(void* const* d_in, const int* in_sizes, int n_in,
                              void* d_out, int out_size) {
    const float* user_w     = (const float*)d_in[0];
    const float* item_w     = (const float*)d_in[1];
    const float* user_delta = (const float*)d_in[2];
    const float* item_delta = (const float*)d_in[3];
    const float* edge_logit = (const float*)d_in[4];
    const int*   cu         = (const int*)d_in[5];
    const int*   ci         = (const int*)d_in[6];
    float* out = (float*)d_out;

    int gEdges = (NUM_EDGES + BT - 1) / BT;
    int gProp  = ((NUM_CU + NUM_CI) * 32 + BT - 1) / BT;

    edge_init_kernel<<<G_EI, BT>>>(edge_logit, cu, ci,
                                   user_w, item_w, user_delta, item_delta);
    scan_kernel<<<NT_TOT, TILE>>>();
    bucket_kernel<<<gEdges, BT>>>(edge_logit, cu, ci);

    prop_kernel<0, false><<<gProp, BT>>>(out);
    prop_kernel<1, false><<<gProp, BT>>>(out);
    prop_kernel<2, true ><<<gProp, BT>>>(out);
}